// round 5
// baseline (speedup 1.0000x reference)
#include <cuda_runtime.h>
#include <math.h>

// ----------------------------------------------------------------------------
// Problem constants
// ----------------------------------------------------------------------------
#define S_LEN 2048
#define BATCH 2
#define DM    1024
#define NH    16
#define DH    64
#define MROWS (BATCH * S_LEN)   // 4096

// ----------------------------------------------------------------------------
// Scratch (static device globals: allocation inside kernel_launch is banned)
// ----------------------------------------------------------------------------
__device__ float  g_q[BATCH * NH * S_LEN * DH];     // [bh][s][dh]
__device__ float  g_k[BATCH * NH * S_LEN * DH];
__device__ float  g_v[BATCH * NH * S_LEN * DH];
__device__ float  g_attn[BATCH * S_LEN * DM];       // [b*S+s][1024]
__device__ float2 g_rope[S_LEN * (DH / 2)];         // (cos, sin) per (s, freq)

// ----------------------------------------------------------------------------
// Packed fp32x2 helpers (Blackwell FFMA2 path — 2x fp32 FMA throughput)
// ----------------------------------------------------------------------------
#define PACKDUP(d, x) asm("mov.b64 %0, {%1, %1};" : "=l"(d) : "r"(__float_as_uint(x)))
#define FFMA2(c, a, b) asm("fma.rn.f32x2 %0, %1, %2, %0;" : "+l"(c) : "l"(a), "l"(b))
#define SCALE2(c, s)   asm("mul.rn.f32x2 %0, %0, %1;" : "+l"(c) : "l"(s))

__device__ __forceinline__ float lo2(unsigned long long p) { return __uint_as_float((unsigned)p); }
__device__ __forceinline__ float hi2(unsigned long long p) { return __uint_as_float((unsigned)(p >> 32)); }
__device__ __forceinline__ unsigned long long dbits(double d) {
    return (unsigned long long)__double_as_longlong(d);
}

// ----------------------------------------------------------------------------
// RoPE table: cos/sin of the fp32-rounded angle, computed with double trig so
// large-argument range reduction is exact (matches the fp32 reference argument
// bit-exactly regardless of fast-math flags).
// ----------------------------------------------------------------------------
__global__ void rope_table_kernel(float2* __restrict__ tab) {
    int idx = blockIdx.x * blockDim.x + threadIdx.x;
    if (idx >= S_LEN * (DH / 2)) return;
    int s = idx >> 5;        // DH/2 == 32
    int i = idx & 31;
    double e = (double)(2 * i) / (double)DH;
    float invf = (float)exp(-e * log(10000.0));
    float ang  = (float)s * invf;        // fp32 rounding like the reference
    double a   = (double)ang;
    tab[idx] = make_float2((float)cos(a), (float)sin(a));
}

// ----------------------------------------------------------------------------
// NT GEMM: C[m][n] = sum_d A[m][d] * W[n][d]   (M=4096, N=1024, K=1024)
// Block tile 64(M) x 128(N), BK=16, 256 threads, 4x8 microtile, f32x2 FMA.
// mode 0: scatter to [bh][s][dh] (V)      mode 1: same + RoPE (Q, K)
// mode 2: plain row-major store (output projection)
// ----------------------------------------------------------------------------
__global__ __launch_bounds__(256) void gemm_nt(const float* __restrict__ A,
                                               const float* __restrict__ W,
                                               float* __restrict__ dst,
                                               int mode) {
    __shared__ __align__(16) float As[16][68];
    __shared__ __align__(16) float Bs[16][132];

    const int tid = threadIdx.x;
    const int tx = tid & 15, ty = tid >> 4;
    const int m0 = (int)blockIdx.y << 6;
    const int n0 = (int)blockIdx.x << 7;
    const int lr = tid >> 2;              // 0..63
    const int lk = (tid & 3) << 2;        // 0,4,8,12

    const float* Ap  = A + (size_t)(m0 + lr) * DM + lk;
    const float* Bp0 = W + (size_t)(n0 + lr) * DM + lk;
    const float* Bp1 = Bp0 + (size_t)64 * DM;

    unsigned long long acc[4][4];
#pragma unroll
    for (int i = 0; i < 4; i++)
#pragma unroll
        for (int j = 0; j < 4; j++) acc[i][j] = 0ull;

    for (int k0 = 0; k0 < DM; k0 += 16) {
        float4 av  = *(const float4*)(Ap + k0);
        float4 b0v = *(const float4*)(Bp0 + k0);
        float4 b1v = *(const float4*)(Bp1 + k0);
        __syncthreads();
        As[lk + 0][lr] = av.x;  As[lk + 1][lr] = av.y;
        As[lk + 2][lr] = av.z;  As[lk + 3][lr] = av.w;
        Bs[lk + 0][lr] = b0v.x; Bs[lk + 1][lr] = b0v.y;
        Bs[lk + 2][lr] = b0v.z; Bs[lk + 3][lr] = b0v.w;
        Bs[lk + 0][lr + 64] = b1v.x; Bs[lk + 1][lr + 64] = b1v.y;
        Bs[lk + 2][lr + 64] = b1v.z; Bs[lk + 3][lr + 64] = b1v.w;
        __syncthreads();
#pragma unroll
        for (int k = 0; k < 16; k++) {
            float4  a  = *(const float4*)&As[k][ty << 2];
            double2 p0 = *(const double2*)&Bs[k][tx << 3];
            double2 p1 = *(const double2*)&Bs[k][(tx << 3) + 4];
            unsigned long long b0 = dbits(p0.x), b1 = dbits(p0.y);
            unsigned long long b2 = dbits(p1.x), b3 = dbits(p1.y);
            unsigned long long ad;
            PACKDUP(ad, a.x);
            FFMA2(acc[0][0], ad, b0); FFMA2(acc[0][1], ad, b1);
            FFMA2(acc[0][2], ad, b2); FFMA2(acc[0][3], ad, b3);
            PACKDUP(ad, a.y);
            FFMA2(acc[1][0], ad, b0); FFMA2(acc[1][1], ad, b1);
            FFMA2(acc[1][2], ad, b2); FFMA2(acc[1][3], ad, b3);
            PACKDUP(ad, a.z);
            FFMA2(acc[2][0], ad, b0); FFMA2(acc[2][1], ad, b1);
            FFMA2(acc[2][2], ad, b2); FFMA2(acc[2][3], ad, b3);
            PACKDUP(ad, a.w);
            FFMA2(acc[3][0], ad, b0); FFMA2(acc[3][1], ad, b1);
            FFMA2(acc[3][2], ad, b2); FFMA2(acc[3][3], ad, b3);
        }
    }

    const int mb = m0 + (ty << 2);
    const int nb = n0 + (tx << 3);
    if (mode == 2) {
#pragma unroll
        for (int i = 0; i < 4; i++) {
            float* o = dst + (size_t)(mb + i) * DM + nb;
            o[0] = lo2(acc[i][0]); o[1] = hi2(acc[i][0]);
            o[2] = lo2(acc[i][1]); o[3] = hi2(acc[i][1]);
            o[4] = lo2(acc[i][2]); o[5] = hi2(acc[i][2]);
            o[6] = lo2(acc[i][3]); o[7] = hi2(acc[i][3]);
        }
    } else {
#pragma unroll
        for (int i = 0; i < 4; i++) {
            int m = mb + i;
            int b = m >> 11;              // /2048
            int s = m & (S_LEN - 1);
#pragma unroll
            for (int pj = 0; pj < 4; pj++) {
                int e  = nb + (pj << 1);  // even
                int h  = e >> 6;
                int dh = e & 63;
                float x1 = lo2(acc[i][pj]);
                float x2 = hi2(acc[i][pj]);
                float* o = dst + ((size_t)((b << 4) + h) * S_LEN + s) * DH + dh;
                if (mode == 1) {
                    float2 cs = g_rope[s * (DH / 2) + (dh >> 1)];
                    o[0] = x1 * cs.x - x2 * cs.y;
                    o[1] = x1 * cs.y + x2 * cs.x;
                } else {
                    o[0] = x1;
                    o[1] = x2;
                }
            }
        }
    }
}

// ----------------------------------------------------------------------------
// Causal flash attention, fp32, f32x2 FMA.
// grid: (32 bh, 32 qt-reversed), 256 threads, 64-row Q tile, 64-key KV tiles.
// Smem = exactly 48KB static: Qs/Ks transposed [dh][row] stride-64 (conflict-
// free for our patterns), Vs XOR-swizzled, P tile aliases Ks.
// ----------------------------------------------------------------------------
__global__ __launch_bounds__(256) void attn_kernel(const float* __restrict__ Q,
                                                   const float* __restrict__ K,
                                                   const float* __restrict__ V,
                                                   float* __restrict__ O) {
    __shared__ __align__(16) float Qs[64][64];
    __shared__ __align__(16) float Ks[64][64];   // aliased as P after scores
    __shared__ __align__(16) float Vs[64 * 64];  // swizzled

    const int tid = threadIdx.x;
    const int tx = tid & 15, ty = tid >> 4;
    const int bh = (int)blockIdx.x;
    const int qt = 31 - (int)blockIdx.y;         // heavy tiles first
    const int q0 = qt << 6;
    const float* qb = Q + ((size_t)bh * S_LEN + q0) * DH;

#pragma unroll
    for (int r = 0; r < 4; r++) {
        int t = tid + (r << 8);
        int row = t & 63, c4 = t >> 6;           // c4 in 0..15
        float4 vq = *(const float4*)(qb + row * DH + (c4 << 2));
        Qs[(c4 << 2) + 0][row] = vq.x; Qs[(c4 << 2) + 1][row] = vq.y;
        Qs[(c4 << 2) + 2][row] = vq.z; Qs[(c4 << 2) + 3][row] = vq.w;
    }

    unsigned long long op[4][2];
    float mrun[4], lrun[4];
#pragma unroll
    for (int i = 0; i < 4; i++) {
        op[i][0] = 0ull; op[i][1] = 0ull;
        mrun[i] = -1e30f; lrun[i] = 0.0f;
    }

    const float L2E = 1.4426950408889634f;

    for (int jt = 0; jt <= qt; ++jt) {
        const int k0 = jt << 6;
        const float* kb = K + ((size_t)bh * S_LEN + k0) * DH;
        const float* vb = V + ((size_t)bh * S_LEN + k0) * DH;

        __syncthreads();  // previous PV (and Q stores on iter 0) complete
#pragma unroll
        for (int r = 0; r < 4; r++) {
            int t = tid + (r << 8);
            int row = t & 63, c4 = t >> 6;
            float4 kv = *(const float4*)(kb + row * DH + (c4 << 2));
            Ks[(c4 << 2) + 0][row] = kv.x; Ks[(c4 << 2) + 1][row] = kv.y;
            Ks[(c4 << 2) + 2][row] = kv.z; Ks[(c4 << 2) + 3][row] = kv.w;
            float4 vv = *(const float4*)(vb + row * DH + (c4 << 2));
            *(float4*)&Vs[(row << 6) + ((c4 ^ (row & 15)) << 2)] = vv;
        }
        __syncthreads();

        // ---- scores S = Q K^T ----
        unsigned long long sp[4][2];
#pragma unroll
        for (int i = 0; i < 4; i++) { sp[i][0] = 0ull; sp[i][1] = 0ull; }
#pragma unroll 8
        for (int k = 0; k < 64; k++) {
            float4  a  = *(const float4*)&Qs[k][ty << 2];
            double2 kk = *(const double2*)&Ks[k][tx << 2];
            unsigned long long b0 = dbits(kk.x), b1 = dbits(kk.y), ad;
            PACKDUP(ad, a.x); FFMA2(sp[0][0], ad, b0); FFMA2(sp[0][1], ad, b1);
            PACKDUP(ad, a.y); FFMA2(sp[1][0], ad, b0); FFMA2(sp[1][1], ad, b1);
            PACKDUP(ad, a.z); FFMA2(sp[2][0], ad, b0); FFMA2(sp[2][1], ad, b1);
            PACKDUP(ad, a.w); FFMA2(sp[3][0], ad, b0); FFMA2(sp[3][1], ad, b1);
        }
        __syncthreads();  // all Ks reads done before P writes (alias)

        float* Ps = &Ks[0][0];
#pragma unroll
        for (int i = 0; i < 4; i++) {
            float s0 = lo2(sp[i][0]) * 0.125f;
            float s1 = hi2(sp[i][0]) * 0.125f;
            float s2 = lo2(sp[i][1]) * 0.125f;
            float s3 = hi2(sp[i][1]) * 0.125f;
            if (jt == qt) {  // diagonal tile: causal mask (k0 == q0)
                int rl = (ty << 2) + i, cl = tx << 2;
                if (cl + 0 > rl) s0 = -1e30f;
                if (cl + 1 > rl) s1 = -1e30f;
                if (cl + 2 > rl) s2 = -1e30f;
                if (cl + 3 > rl) s3 = -1e30f;
            }
            float mt = fmaxf(fmaxf(s0, s1), fmaxf(s2, s3));
#pragma unroll
            for (int w = 8; w >= 1; w >>= 1)
                mt = fmaxf(mt, __shfl_xor_sync(0xffffffffu, mt, w));
            float mnew = fmaxf(mrun[i], mt);
            float al = exp2f((mrun[i] - mnew) * L2E);
            mrun[i] = mnew;
            float p0 = exp2f((s0 - mnew) * L2E);
            float p1 = exp2f((s1 - mnew) * L2E);
            float p2 = exp2f((s2 - mnew) * L2E);
            float p3 = exp2f((s3 - mnew) * L2E);
            float rs = (p0 + p1) + (p2 + p3);
#pragma unroll
            for (int w = 8; w >= 1; w >>= 1)
                rs += __shfl_xor_sync(0xffffffffu, rs, w);
            lrun[i] = lrun[i] * al + rs;
            unsigned long long alp;
            PACKDUP(alp, al);
            SCALE2(op[i][0], alp);
            SCALE2(op[i][1], alp);
            *(float4*)&Ps[(((ty << 2) + i) << 6) + (tx << 2)] =
                make_float4(p0, p1, p2, p3);
        }
        __syncthreads();

        // ---- O += P V ----
#pragma unroll 4
        for (int k4 = 0; k4 < 64; k4 += 4) {
            float4 pr[4];
#pragma unroll
            for (int i = 0; i < 4; i++)
                pr[i] = *(const float4*)&Ps[(((ty << 2) + i) << 6) + k4];
#pragma unroll
            for (int kk = 0; kk < 4; kk++) {
                int krow = k4 + kk;
                double2 vv = *(const double2*)
                    &Vs[(krow << 6) + ((tx ^ (krow & 15)) << 2)];
                unsigned long long v0 = dbits(vv.x), v1 = dbits(vv.y), pd;
                PACKDUP(pd, ((const float*)&pr[0])[kk]);
                FFMA2(op[0][0], pd, v0); FFMA2(op[0][1], pd, v1);
                PACKDUP(pd, ((const float*)&pr[1])[kk]);
                FFMA2(op[1][0], pd, v0); FFMA2(op[1][1], pd, v1);
                PACKDUP(pd, ((const float*)&pr[2])[kk]);
                FFMA2(op[2][0], pd, v0); FFMA2(op[2][1], pd, v1);
                PACKDUP(pd, ((const float*)&pr[3])[kk]);
                FFMA2(op[3][0], pd, v0); FFMA2(op[3][1], pd, v1);
            }
        }
    }

    // ---- normalize + write [b][s][h*64+dv] ----
    const int b = bh >> 4, h = bh & 15;
#pragma unroll
    for (int i = 0; i < 4; i++) {
        float inv = 1.0f / lrun[i];
        int srow = q0 + (ty << 2) + i;
        float* o = O + ((size_t)(b * S_LEN + srow)) * DM + (h << 6) + (tx << 2);
        o[0] = lo2(op[i][0]) * inv;
        o[1] = hi2(op[i][0]) * inv;
        o[2] = lo2(op[i][1]) * inv;
        o[3] = hi2(op[i][1]) * inv;
    }
}

// ----------------------------------------------------------------------------
// Launch
// ----------------------------------------------------------------------------
extern "C" void kernel_launch(void* const* d_in, const int* in_sizes, int n_in,
                              void* d_out, int out_size) {
    (void)in_sizes; (void)n_in; (void)out_size;
    const float* X  = (const float*)d_in[0];
    const float* Wq = (const float*)d_in[1];
    const float* Wk = (const float*)d_in[2];
    const float* Wv = (const float*)d_in[3];
    const float* Wo = (const float*)d_in[4];
    float* out = (float*)d_out;

    float *gq, *gk, *gv, *ga;
    float2* grope;
    cudaGetSymbolAddress((void**)&gq, g_q);
    cudaGetSymbolAddress((void**)&gk, g_k);
    cudaGetSymbolAddress((void**)&gv, g_v);
    cudaGetSymbolAddress((void**)&ga, g_attn);
    cudaGetSymbolAddress((void**)&grope, g_rope);

    rope_table_kernel<<<256, 256>>>(grope);

    dim3 gg(DM / 128, MROWS / 64);  // (8, 64)
    gemm_nt<<<gg, 256>>>(X, Wq, gq, 1);
    gemm_nt<<<gg, 256>>>(X, Wk, gk, 1);
    gemm_nt<<<gg, 256>>>(X, Wv, gv, 0);

    attn_kernel<<<dim3(BATCH * NH, S_LEN / 64), 256>>>(gq, gk, gv, ga);

    gemm_nt<<<gg, 256>>>(ga, Wo, out, 2);
}

// round 7
// speedup vs baseline: 1.5488x; 1.5488x over previous
#include <cuda_runtime.h>
#include <math.h>

// ----------------------------------------------------------------------------
// Problem constants
// ----------------------------------------------------------------------------
#define S_LEN 2048
#define BATCH 2
#define DM    1024
#define NH    16
#define DH    64
#define MROWS (BATCH * S_LEN)   // 4096

// ----------------------------------------------------------------------------
// Scratch (static device globals: allocation inside kernel_launch is banned)
// ----------------------------------------------------------------------------
__device__ float  g_q[BATCH * NH * S_LEN * DH];     // [bh][s][dh]
__device__ float  g_k[BATCH * NH * S_LEN * DH];
__device__ float  g_v[BATCH * NH * S_LEN * DH];
__device__ float  g_attn[BATCH * S_LEN * DM];       // [b*S+s][1024]
__device__ float2 g_rope[S_LEN * (DH / 2)];         // (cos, sin) per (s, freq)

// ----------------------------------------------------------------------------
// Packed fp32x2 helpers (Blackwell FFMA2 path — 2x fp32 FMA throughput)
// ----------------------------------------------------------------------------
#define PACKDUP(d, x) asm("mov.b64 %0, {%1, %1};" : "=l"(d) : "r"(__float_as_uint(x)))
#define FFMA2(c, a, b) asm("fma.rn.f32x2 %0, %1, %2, %0;" : "+l"(c) : "l"(a), "l"(b))
#define SCALE2(c, s)   asm("mul.rn.f32x2 %0, %0, %1;" : "+l"(c) : "l"(s))

__device__ __forceinline__ float lo2(unsigned long long p) { return __uint_as_float((unsigned)p); }
__device__ __forceinline__ float hi2(unsigned long long p) { return __uint_as_float((unsigned)(p >> 32)); }
__device__ __forceinline__ unsigned long long dbits(double d) {
    return (unsigned long long)__double_as_longlong(d);
}

// ----------------------------------------------------------------------------
// RoPE table: cos/sin of the fp32-rounded angle, computed with double trig so
// large-argument range reduction is exact (matches the fp32 reference argument
// bit-exactly regardless of fast-math flags).
// ----------------------------------------------------------------------------
__global__ void rope_table_kernel(float2* __restrict__ tab) {
    int idx = blockIdx.x * blockDim.x + threadIdx.x;
    if (idx >= S_LEN * (DH / 2)) return;
    int s = idx >> 5;        // DH/2 == 32
    int i = idx & 31;
    double e = (double)(2 * i) / (double)DH;
    float invf = (float)exp(-e * log(10000.0));
    float ang  = (float)s * invf;        // fp32 rounding like the reference
    double a   = (double)ang;
    tab[idx] = make_float2((float)cos(a), (float)sin(a));
}

// ----------------------------------------------------------------------------
// NT GEMM body: C[m][n] = sum_d A[m][d] * W[n][d]   (M=4096, N=1024, K=1024)
// Block tile 128x128, BK=16, 256 threads, 8x8 microtile, double-buffered smem,
// f32x2 FMA (acc packed along N).
//   B smem layout per k-row (144 floats):  n = 8*g + j  ->
//       (j<4 ? 0 : 72) + 4*g + (j&3)
//   so thread tx reads its 8 columns as two contiguous 16B LDS.128 (bank-free)
//   and the transposed stores of the two k-halves hit disjoint bank sets.
//   A rows padded to 144 so the two k-half store groups are 16 banks apart.
// mode 0: scatter to [bh][s][dh] (V)      mode 1: same + RoPE (Q, K)
// mode 2: plain row-major store (output projection)
// ----------------------------------------------------------------------------
__device__ __forceinline__ void gemm_body(const float* __restrict__ A,
                                          const float* __restrict__ W,
                                          float* __restrict__ dst,
                                          int mode) {
    __shared__ __align__(16) float As[2][16][144];
    __shared__ __align__(16) float Bs[2][16][144];

    const int tid = threadIdx.x;
    const int tx = tid & 15, ty = tid >> 4;
    const int m0 = (int)blockIdx.y << 7;
    const int n0 = (int)blockIdx.x << 7;

    // loaders: each thread owns one row (A: m-row / B: n-row) and one k-half
    const int lr = tid >> 1;              // 0..127
    const int lk = (tid & 1) << 2;        // 0 or 4
    const int nmod = lr & 7;
    const int bcol = ((nmod & 4) ? 72 : 0) + ((lr >> 3) << 2) + (nmod & 3);

    const float* Ap = A + (size_t)(m0 + lr) * DM + lk;
    const float* Bp = W + (size_t)(n0 + lr) * DM + lk;

    unsigned long long acc[8][4];
#pragma unroll
    for (int i = 0; i < 8; i++)
#pragma unroll
        for (int j = 0; j < 4; j++) acc[i][j] = 0ull;

    // preload tile 0
    {
        float4 a0v = *(const float4*)(Ap);
        float4 a1v = *(const float4*)(Ap + 8);
        float4 b0v = *(const float4*)(Bp);
        float4 b1v = *(const float4*)(Bp + 8);
        As[0][lk + 0][lr] = a0v.x; As[0][lk + 1][lr] = a0v.y;
        As[0][lk + 2][lr] = a0v.z; As[0][lk + 3][lr] = a0v.w;
        As[0][lk + 8][lr] = a1v.x; As[0][lk + 9][lr] = a1v.y;
        As[0][lk +10][lr] = a1v.z; As[0][lk +11][lr] = a1v.w;
        Bs[0][lk + 0][bcol] = b0v.x; Bs[0][lk + 1][bcol] = b0v.y;
        Bs[0][lk + 2][bcol] = b0v.z; Bs[0][lk + 3][bcol] = b0v.w;
        Bs[0][lk + 8][bcol] = b1v.x; Bs[0][lk + 9][bcol] = b1v.y;
        Bs[0][lk +10][bcol] = b1v.z; Bs[0][lk +11][bcol] = b1v.w;
    }
    __syncthreads();

#define ROWFMA(i, as_) { unsigned long long ad_; PACKDUP(ad_, as_);            \
        FFMA2(acc[i][0], ad_, b0); FFMA2(acc[i][1], ad_, b1);                  \
        FFMA2(acc[i][2], ad_, b2); FFMA2(acc[i][3], ad_, b3); }

    int buf = 0;
    for (int k0 = 16; k0 <= DM; k0 += 16) {
        float4 a0v, a1v, b0v, b1v;
        const bool more = (k0 < DM);
        if (more) {
            a0v = *(const float4*)(Ap + k0);
            a1v = *(const float4*)(Ap + k0 + 8);
            b0v = *(const float4*)(Bp + k0);
            b1v = *(const float4*)(Bp + k0 + 8);
        }
#pragma unroll
        for (int k = 0; k < 16; k++) {
            float4  af0 = *(const float4*)&As[buf][k][ty << 3];
            float4  af1 = *(const float4*)&As[buf][k][(ty << 3) + 4];
            double2 q0  = *(const double2*)&Bs[buf][k][tx << 2];
            double2 q1  = *(const double2*)&Bs[buf][k][72 + (tx << 2)];
            unsigned long long b0 = dbits(q0.x), b1 = dbits(q0.y);
            unsigned long long b2 = dbits(q1.x), b3 = dbits(q1.y);
            ROWFMA(0, af0.x); ROWFMA(1, af0.y);
            ROWFMA(2, af0.z); ROWFMA(3, af0.w);
            ROWFMA(4, af1.x); ROWFMA(5, af1.y);
            ROWFMA(6, af1.z); ROWFMA(7, af1.w);
        }
        if (more) {
            int nb_ = buf ^ 1;
            As[nb_][lk + 0][lr] = a0v.x; As[nb_][lk + 1][lr] = a0v.y;
            As[nb_][lk + 2][lr] = a0v.z; As[nb_][lk + 3][lr] = a0v.w;
            As[nb_][lk + 8][lr] = a1v.x; As[nb_][lk + 9][lr] = a1v.y;
            As[nb_][lk +10][lr] = a1v.z; As[nb_][lk +11][lr] = a1v.w;
            Bs[nb_][lk + 0][bcol] = b0v.x; Bs[nb_][lk + 1][bcol] = b0v.y;
            Bs[nb_][lk + 2][bcol] = b0v.z; Bs[nb_][lk + 3][bcol] = b0v.w;
            Bs[nb_][lk + 8][bcol] = b1v.x; Bs[nb_][lk + 9][bcol] = b1v.y;
            Bs[nb_][lk +10][bcol] = b1v.z; Bs[nb_][lk +11][bcol] = b1v.w;
        }
        __syncthreads();
        buf ^= 1;
    }
#undef ROWFMA

    const int mb = m0 + (ty << 3);
    const int nb = n0 + (tx << 3);
    if (mode == 2) {
#pragma unroll
        for (int i = 0; i < 8; i++) {
            float* o = dst + (size_t)(mb + i) * DM + nb;
            o[0] = lo2(acc[i][0]); o[1] = hi2(acc[i][0]);
            o[2] = lo2(acc[i][1]); o[3] = hi2(acc[i][1]);
            o[4] = lo2(acc[i][2]); o[5] = hi2(acc[i][2]);
            o[6] = lo2(acc[i][3]); o[7] = hi2(acc[i][3]);
        }
    } else {
#pragma unroll
        for (int i = 0; i < 8; i++) {
            int m = mb + i;
            int b = m >> 11;              // /2048
            int s = m & (S_LEN - 1);
#pragma unroll
            for (int pj = 0; pj < 4; pj++) {
                int e  = nb + (pj << 1);  // even
                int h  = e >> 6;
                int dh = e & 63;
                float x1 = lo2(acc[i][pj]);
                float x2 = hi2(acc[i][pj]);
                float* o = dst + ((size_t)((b << 4) + h) * S_LEN + s) * DH + dh;
                if (mode == 1) {
                    float2 cs = g_rope[s * (DH / 2) + (dh >> 1)];
                    o[0] = x1 * cs.x - x2 * cs.y;
                    o[1] = x1 * cs.y + x2 * cs.x;
                } else {
                    o[0] = x1;
                    o[1] = x2;
                }
            }
        }
    }
}

// Fused QKV: blockIdx.z selects projection (0=Q rope, 1=K rope, 2=V plain)
__global__ __launch_bounds__(256, 2) void gemm_qkv(const float* __restrict__ X,
                                                   const float* __restrict__ Wq,
                                                   const float* __restrict__ Wk,
                                                   const float* __restrict__ Wv,
                                                   float* __restrict__ dq,
                                                   float* __restrict__ dk,
                                                   float* __restrict__ dv) {
    const int z = blockIdx.z;
    const float* W = (z == 0) ? Wq : (z == 1) ? Wk : Wv;
    float* d       = (z == 0) ? dq : (z == 1) ? dk : dv;
    gemm_body(X, W, d, (z == 2) ? 0 : 1);
}

__global__ __launch_bounds__(256, 2) void gemm_out(const float* __restrict__ A,
                                                   const float* __restrict__ W,
                                                   float* __restrict__ dst) {
    gemm_body(A, W, dst, 2);
}

// ----------------------------------------------------------------------------
// Causal flash attention, fp32, f32x2 FMA (unchanged from R5 — passing).
// grid: (32 bh, 32 qt-reversed), 256 threads, 64-row Q tile, 64-key KV tiles.
// ----------------------------------------------------------------------------
__global__ __launch_bounds__(256) void attn_kernel(const float* __restrict__ Q,
                                                   const float* __restrict__ K,
                                                   const float* __restrict__ V,
                                                   float* __restrict__ O) {
    __shared__ __align__(16) float Qs[64][64];
    __shared__ __align__(16) float Ks[64][64];   // aliased as P after scores
    __shared__ __align__(16) float Vs[64 * 64];  // swizzled

    const int tid = threadIdx.x;
    const int tx = tid & 15, ty = tid >> 4;
    const int bh = (int)blockIdx.x;
    const int qt = 31 - (int)blockIdx.y;         // heavy tiles first
    const int q0 = qt << 6;
    const float* qb = Q + ((size_t)bh * S_LEN + q0) * DH;

#pragma unroll
    for (int r = 0; r < 4; r++) {
        int t = tid + (r << 8);
        int row = t & 63, c4 = t >> 6;           // c4 in 0..15
        float4 vq = *(const float4*)(qb + row * DH + (c4 << 2));
        Qs[(c4 << 2) + 0][row] = vq.x; Qs[(c4 << 2) + 1][row] = vq.y;
        Qs[(c4 << 2) + 2][row] = vq.z; Qs[(c4 << 2) + 3][row] = vq.w;
    }

    unsigned long long op[4][2];
    float mrun[4], lrun[4];
#pragma unroll
    for (int i = 0; i < 4; i++) {
        op[i][0] = 0ull; op[i][1] = 0ull;
        mrun[i] = -1e30f; lrun[i] = 0.0f;
    }

    const float L2E = 1.4426950408889634f;

    for (int jt = 0; jt <= qt; ++jt) {
        const int k0 = jt << 6;
        const float* kb = K + ((size_t)bh * S_LEN + k0) * DH;
        const float* vb = V + ((size_t)bh * S_LEN + k0) * DH;

        __syncthreads();  // previous PV (and Q stores on iter 0) complete
#pragma unroll
        for (int r = 0; r < 4; r++) {
            int t = tid + (r << 8);
            int row = t & 63, c4 = t >> 6;
            float4 kv = *(const float4*)(kb + row * DH + (c4 << 2));
            Ks[(c4 << 2) + 0][row] = kv.x; Ks[(c4 << 2) + 1][row] = kv.y;
            Ks[(c4 << 2) + 2][row] = kv.z; Ks[(c4 << 2) + 3][row] = kv.w;
            float4 vv = *(const float4*)(vb + row * DH + (c4 << 2));
            *(float4*)&Vs[(row << 6) + ((c4 ^ (row & 15)) << 2)] = vv;
        }
        __syncthreads();

        // ---- scores S = Q K^T ----
        unsigned long long sp[4][2];
#pragma unroll
        for (int i = 0; i < 4; i++) { sp[i][0] = 0ull; sp[i][1] = 0ull; }
#pragma unroll 8
        for (int k = 0; k < 64; k++) {
            float4  a  = *(const float4*)&Qs[k][ty << 2];
            double2 kk = *(const double2*)&Ks[k][tx << 2];
            unsigned long long b0 = dbits(kk.x), b1 = dbits(kk.y), ad;
            PACKDUP(ad, a.x); FFMA2(sp[0][0], ad, b0); FFMA2(sp[0][1], ad, b1);
            PACKDUP(ad, a.y); FFMA2(sp[1][0], ad, b0); FFMA2(sp[1][1], ad, b1);
            PACKDUP(ad, a.z); FFMA2(sp[2][0], ad, b0); FFMA2(sp[2][1], ad, b1);
            PACKDUP(ad, a.w); FFMA2(sp[3][0], ad, b0); FFMA2(sp[3][1], ad, b1);
        }
        __syncthreads();  // all Ks reads done before P writes (alias)

        float* Ps = &Ks[0][0];
#pragma unroll
        for (int i = 0; i < 4; i++) {
            float s0 = lo2(sp[i][0]) * 0.125f;
            float s1 = hi2(sp[i][0]) * 0.125f;
            float s2 = lo2(sp[i][1]) * 0.125f;
            float s3 = hi2(sp[i][1]) * 0.125f;
            if (jt == qt) {  // diagonal tile: causal mask (k0 == q0)
                int rl = (ty << 2) + i, cl = tx << 2;
                if (cl + 0 > rl) s0 = -1e30f;
                if (cl + 1 > rl) s1 = -1e30f;
                if (cl + 2 > rl) s2 = -1e30f;
                if (cl + 3 > rl) s3 = -1e30f;
            }
            float mt = fmaxf(fmaxf(s0, s1), fmaxf(s2, s3));
#pragma unroll
            for (int w = 8; w >= 1; w >>= 1)
                mt = fmaxf(mt, __shfl_xor_sync(0xffffffffu, mt, w));
            float mnew = fmaxf(mrun[i], mt);
            float al = exp2f((mrun[i] - mnew) * L2E);
            mrun[i] = mnew;
            float p0 = exp2f((s0 - mnew) * L2E);
            float p1 = exp2f((s1 - mnew) * L2E);
            float p2 = exp2f((s2 - mnew) * L2E);
            float p3 = exp2f((s3 - mnew) * L2E);
            float rs = (p0 + p1) + (p2 + p3);
#pragma unroll
            for (int w = 8; w >= 1; w >>= 1)
                rs += __shfl_xor_sync(0xffffffffu, rs, w);
            lrun[i] = lrun[i] * al + rs;
            unsigned long long alp;
            PACKDUP(alp, al);
            SCALE2(op[i][0], alp);
            SCALE2(op[i][1], alp);
            *(float4*)&Ps[(((ty << 2) + i) << 6) + (tx << 2)] =
                make_float4(p0, p1, p2, p3);
        }
        __syncthreads();

        // ---- O += P V ----
#pragma unroll 4
        for (int k4 = 0; k4 < 64; k4 += 4) {
            float4 pr[4];
#pragma unroll
            for (int i = 0; i < 4; i++)
                pr[i] = *(const float4*)&Ps[(((ty << 2) + i) << 6) + k4];
#pragma unroll
            for (int kk = 0; kk < 4; kk++) {
                int krow = k4 + kk;
                double2 vv = *(const double2*)
                    &Vs[(krow << 6) + ((tx ^ (krow & 15)) << 2)];
                unsigned long long v0 = dbits(vv.x), v1 = dbits(vv.y), pd;
                PACKDUP(pd, ((const float*)&pr[0])[kk]);
                FFMA2(op[0][0], pd, v0); FFMA2(op[0][1], pd, v1);
                PACKDUP(pd, ((const float*)&pr[1])[kk]);
                FFMA2(op[1][0], pd, v0); FFMA2(op[1][1], pd, v1);
                PACKDUP(pd, ((const float*)&pr[2])[kk]);
                FFMA2(op[2][0], pd, v0); FFMA2(op[2][1], pd, v1);
                PACKDUP(pd, ((const float*)&pr[3])[kk]);
                FFMA2(op[3][0], pd, v0); FFMA2(op[3][1], pd, v1);
            }
        }
    }

    // ---- normalize + write [b][s][h*64+dv] ----
    const int b = bh >> 4, h = bh & 15;
#pragma unroll
    for (int i = 0; i < 4; i++) {
        float inv = 1.0f / lrun[i];
        int srow = q0 + (ty << 2) + i;
        float* o = O + ((size_t)(b * S_LEN + srow)) * DM + (h << 6) + (tx << 2);
        o[0] = lo2(op[i][0]) * inv;
        o[1] = hi2(op[i][0]) * inv;
        o[2] = lo2(op[i][1]) * inv;
        o[3] = hi2(op[i][1]) * inv;
    }
}

// ----------------------------------------------------------------------------
// Launch
// ----------------------------------------------------------------------------
extern "C" void kernel_launch(void* const* d_in, const int* in_sizes, int n_in,
                              void* d_out, int out_size) {
    (void)in_sizes; (void)n_in; (void)out_size;
    const float* X  = (const float*)d_in[0];
    const float* Wq = (const float*)d_in[1];
    const float* Wk = (const float*)d_in[2];
    const float* Wv = (const float*)d_in[3];
    const float* Wo = (const float*)d_in[4];
    float* out = (float*)d_out;

    float *gq, *gk, *gv, *ga;
    float2* grope;
    cudaGetSymbolAddress((void**)&gq, g_q);
    cudaGetSymbolAddress((void**)&gk, g_k);
    cudaGetSymbolAddress((void**)&gv, g_v);
    cudaGetSymbolAddress((void**)&ga, g_attn);
    cudaGetSymbolAddress((void**)&grope, g_rope);

    rope_table_kernel<<<256, 256>>>(grope);

    dim3 gqkv(DM / 128, MROWS / 128, 3);   // (8, 32, 3)
    gemm_qkv<<<gqkv, 256>>>(X, Wq, Wk, Wv, gq, gk, gv);

    attn_kernel<<<dim3(BATCH * NH, S_LEN / 64), 256>>>(gq, gk, gv, ga);

    dim3 go(DM / 128, MROWS / 128);        // (8, 32)
    gemm_out<<<go, 256>>>(ga, Wo, out);
}

// round 14
// speedup vs baseline: 2.1373x; 1.3800x over previous
#include <cuda_runtime.h>
#include <cuda_bf16.h>
#include <math.h>
#include <stdint.h>

// ----------------------------------------------------------------------------
// Problem constants
// ----------------------------------------------------------------------------
#define S_LEN 2048
#define BATCH 2
#define DM    1024
#define NH    16
#define DH    64
#define MROWS (BATCH * S_LEN)   // 4096

// ----------------------------------------------------------------------------
// Scratch (static device globals: allocation inside kernel_launch is banned)
// ----------------------------------------------------------------------------
__device__ float  g_q[BATCH * NH * S_LEN * DH];     // [bh][s][dh]
__device__ float  g_k[BATCH * NH * S_LEN * DH];
__device__ float  g_v[BATCH * NH * S_LEN * DH];
__device__ float  g_attn[BATCH * S_LEN * DM];       // [b*S+s][1024]
__device__ float2 g_rope[S_LEN * (DH / 2)];         // (cos, sin) per (s, freq)

// bf16 hi/lo splits for tensor-core GEMMs
__device__ __align__(16) __nv_bfloat16 g_xh[MROWS * DM];
__device__ __align__(16) __nv_bfloat16 g_xl[MROWS * DM];
__device__ __align__(16) __nv_bfloat16 g_wh[4 * DM * DM];   // Wq,Wk,Wv,Wo hi
__device__ __align__(16) __nv_bfloat16 g_wl[4 * DM * DM];   // Wq,Wk,Wv,Wo lo

// ----------------------------------------------------------------------------
// Packed fp32x2 helpers (attention kernel)
// ----------------------------------------------------------------------------
#define PACKDUP(d, x) asm("mov.b64 %0, {%1, %1};" : "=l"(d) : "r"(__float_as_uint(x)))
#define FFMA2(c, a, b) asm("fma.rn.f32x2 %0, %1, %2, %0;" : "+l"(c) : "l"(a), "l"(b))
#define SCALE2(c, s)   asm("mul.rn.f32x2 %0, %0, %1;" : "+l"(c) : "l"(s))

__device__ __forceinline__ float lo2(unsigned long long p) { return __uint_as_float((unsigned)p); }
__device__ __forceinline__ float hi2(unsigned long long p) { return __uint_as_float((unsigned)(p >> 32)); }
__device__ __forceinline__ unsigned long long dbits(double d) {
    return (unsigned long long)__double_as_longlong(d);
}

// ----------------------------------------------------------------------------
// mma.sync / ldmatrix helpers (sm_80+ PTX — assembles under compute_103)
// ----------------------------------------------------------------------------
__device__ __forceinline__ uint32_t smem_u32(const void* p) {
    uint32_t a;
    asm("{ .reg .u64 t; cvta.to.shared.u64 t, %1; cvt.u32.u64 %0, t; }" : "=r"(a) : "l"(p));
    return a;
}
__device__ __forceinline__ void ldsm4(uint32_t (&r)[4], uint32_t addr) {
    asm volatile("ldmatrix.sync.aligned.m8n8.x4.shared.b16 {%0,%1,%2,%3}, [%4];"
                 : "=r"(r[0]), "=r"(r[1]), "=r"(r[2]), "=r"(r[3]) : "r"(addr));
}
__device__ __forceinline__ void mma16816(float (&d)[4], const uint32_t (&a)[4],
                                         uint32_t b0, uint32_t b1) {
    asm volatile(
        "mma.sync.aligned.m16n8k16.row.col.f32.bf16.bf16.f32 "
        "{%0,%1,%2,%3}, {%4,%5,%6,%7}, {%8,%9}, {%0,%1,%2,%3};"
        : "+f"(d[0]), "+f"(d[1]), "+f"(d[2]), "+f"(d[3])
        : "r"(a[0]), "r"(a[1]), "r"(a[2]), "r"(a[3]), "r"(b0), "r"(b1));
}

// ----------------------------------------------------------------------------
// RoPE table (fp32-rounded angle, double trig for exact range reduction)
// ----------------------------------------------------------------------------
__global__ void rope_table_kernel(float2* __restrict__ tab) {
    int idx = blockIdx.x * blockDim.x + threadIdx.x;
    if (idx >= S_LEN * (DH / 2)) return;
    int s = idx >> 5;
    int i = idx & 31;
    double e = (double)(2 * i) / (double)DH;
    float invf = (float)exp(-e * log(10000.0));
    float ang  = (float)s * invf;
    double a   = (double)ang;
    tab[idx] = make_float2((float)cos(a), (float)sin(a));
}

// ----------------------------------------------------------------------------
// bf16 hi/lo split: h = bf16(x), l = bf16(x - h)
// ----------------------------------------------------------------------------
__global__ void split_kernel(const float* __restrict__ x,
                             __nv_bfloat16* __restrict__ h,
                             __nv_bfloat16* __restrict__ l, int n4) {
    int i = blockIdx.x * blockDim.x + threadIdx.x;
    if (i >= n4) return;
    float4 v = ((const float4*)x)[i];
    float a[4] = {v.x, v.y, v.z, v.w};
    __nv_bfloat162 hh[2], ll[2];
#pragma unroll
    for (int j = 0; j < 2; j++) {
        __nv_bfloat16 h0 = __float2bfloat16(a[2 * j]);
        __nv_bfloat16 h1 = __float2bfloat16(a[2 * j + 1]);
        __nv_bfloat16 l0 = __float2bfloat16(a[2 * j] - __bfloat162float(h0));
        __nv_bfloat16 l1 = __float2bfloat16(a[2 * j + 1] - __bfloat162float(h1));
        hh[j].x = h0; hh[j].y = h1;
        ll[j].x = l0; ll[j].y = l1;
    }
    ((__nv_bfloat162*)h)[2 * i]     = hh[0];
    ((__nv_bfloat162*)h)[2 * i + 1] = hh[1];
    ((__nv_bfloat162*)l)[2 * i]     = ll[0];
    ((__nv_bfloat162*)l)[2 * i + 1] = ll[1];
}

// ----------------------------------------------------------------------------
// mma.sync NT GEMM: D[m][n] = sum_k A[m][k]*B[n][k], bf16 split operands:
// D = Ah*Bh + Al*Bh + Ah*Bl  ==  one logical K=3072 bf16 GEMM, fp32 accum.
// Tile 128x128, 48 K-chunks of 64 bf16 (SW128 128-byte smem rows), double
// buffer, 8 warps in 2(M)x4(N), warp tile 64x32, ldmatrix + m16n8k16.
// mode 0: scatter to [bh][s][dh]   mode 1: same + RoPE   mode 2: row-major
// ----------------------------------------------------------------------------
#define GA0 0
#define GA1 16384
#define GB0 32768
#define GB1 49152
#define GSMEM_SZ 65536

__device__ __forceinline__ void gemm_mma_body(const __nv_bfloat16* __restrict__ Ah,
                                              const __nv_bfloat16* __restrict__ Al,
                                              const __nv_bfloat16* __restrict__ Bh,
                                              const __nv_bfloat16* __restrict__ Bl,
                                              float* __restrict__ dst, int mode) {
    extern __shared__ char smem[];
    const uint32_t sb = smem_u32(smem);
    const int tid  = threadIdx.x;
    const int wid  = tid >> 5, lane = tid & 31;
    const int wm   = wid & 1;        // 0..1 -> 64-row half
    const int wn   = wid >> 1;       // 0..3 -> 32-col quarter
    const int m0 = (int)blockIdx.y << 7;
    const int n0 = (int)blockIdx.x << 7;

    // --- loader indexing (each thread: 4 rows x 16B, SW128 swizzle) ---
    const int r8  = tid >> 3;        // 0..31
    const int c16 = tid & 7;         // 16B unit

    auto ldg_chunk = [&](int c, uint4 (&ra)[4], uint4 (&rb)[4]) {
        int seg = c >> 4, ko = (c & 15) << 6;
        const __nv_bfloat16* As = (seg == 1) ? Al : Ah;
        const __nv_bfloat16* Bs = (seg == 2) ? Bl : Bh;
#pragma unroll
        for (int r = 0; r < 4; r++) {
            int rr = (r << 5) + r8;
            ra[r] = *(const uint4*)(As + (size_t)(m0 + rr) * DM + ko + (c16 << 3));
            rb[r] = *(const uint4*)(Bs + (size_t)(n0 + rr) * DM + ko + (c16 << 3));
        }
    };
    // NOTE: takes BYTE OFFSETS into the dynamic smem window (generic ptr math).
    auto sts_chunk = [&](uint32_t aofs, uint32_t bofs,
                         const uint4 (&ra)[4], const uint4 (&rb)[4]) {
#pragma unroll
        for (int r = 0; r < 4; r++) {
            int rr = (r << 5) + r8;
            uint32_t off = (rr << 7) + ((c16 << 4) ^ ((rr & 7) << 4));
            *(uint4*)(smem + aofs + off) = ra[r];
            *(uint4*)(smem + bofs + off) = rb[r];
        }
    };

    // --- precomputed swizzled ldmatrix offsets (relative to buffer base) ---
    uint32_t aoff[4][4], boff[2][4];
    {
        int arow = (wm << 6) + (((lane >> 3) & 1) << 3) + (lane & 7);
        int akb  = ((lane >> 4) & 1) << 4;
        int brow = (wn << 5) + (((lane >> 4) & 1) << 3) + (lane & 7);
        int bkb  = ((lane >> 3) & 1) << 4;
#pragma unroll
        for (int kk = 0; kk < 4; kk++) {
#pragma unroll
            for (int mt = 0; mt < 4; mt++) {
                int row = arow + (mt << 4);
                aoff[mt][kk] = (row << 7) + (((kk << 5) + akb) ^ ((row & 7) << 4));
            }
#pragma unroll
            for (int nb = 0; nb < 2; nb++) {
                int row = brow + (nb << 4);
                boff[nb][kk] = (row << 7) + (((kk << 5) + bkb) ^ ((row & 7) << 4));
            }
        }
    }

    float acc[4][4][4];
#pragma unroll
    for (int i = 0; i < 4; i++)
#pragma unroll
        for (int j = 0; j < 4; j++)
#pragma unroll
            for (int t = 0; t < 4; t++) acc[i][j][t] = 0.0f;

    // prolog: chunk 0 -> buffer 0  (plain offsets — the R9 bug was sb+offset here)
    {
        uint4 ra[4], rb[4];
        ldg_chunk(0, ra, rb);
        sts_chunk(GA0, GB0, ra, rb);
    }
    __syncthreads();

    for (int c = 0; c < 48; c++) {
        const int s = c & 1;
        const uint32_t abase = sb + (s ? GA1 : GA0);   // shared-space addr for ldmatrix
        const uint32_t bbase = sb + (s ? GB1 : GB0);
        uint4 ra[4], rb[4];
        const bool more = (c < 47);
        if (more) ldg_chunk(c + 1, ra, rb);

#pragma unroll
        for (int kk = 0; kk < 4; kk++) {
            uint32_t af[4][4], bf[2][4];
#pragma unroll
            for (int mt = 0; mt < 4; mt++) ldsm4(af[mt], abase + aoff[mt][kk]);
#pragma unroll
            for (int nb = 0; nb < 2; nb++) ldsm4(bf[nb], bbase + boff[nb][kk]);
#pragma unroll
            for (int mt = 0; mt < 4; mt++)
#pragma unroll
                for (int nt = 0; nt < 4; nt++)
                    mma16816(acc[mt][nt], af[mt],
                             bf[nt >> 1][(nt & 1) << 1],
                             bf[nt >> 1][((nt & 1) << 1) + 1]);
        }
        if (more) {
            // write the other buffer: plain byte offsets
            sts_chunk(s ? GA0 : GA1, s ? GB0 : GB1, ra, rb);
        }
        __syncthreads();
    }

    // ---- epilogue ----
    const int er = (lane >> 2);
    const int ec = (lane & 3) << 1;
#pragma unroll
    for (int mt = 0; mt < 4; mt++) {
#pragma unroll
        for (int half = 0; half < 2; half++) {
            int m = m0 + (wm << 6) + (mt << 4) + (half << 3) + er;
            if (mode == 2) {
                float* o = dst + (size_t)m * DM + n0 + (wn << 5) + ec;
#pragma unroll
                for (int nt = 0; nt < 4; nt++) {
                    o[(nt << 3) + 0] = acc[mt][nt][(half << 1) + 0];
                    o[(nt << 3) + 1] = acc[mt][nt][(half << 1) + 1];
                }
            } else {
                const int b = m >> 11, sidx = m & (S_LEN - 1);
#pragma unroll
                for (int nt = 0; nt < 4; nt++) {
                    int n  = n0 + (wn << 5) + (nt << 3) + ec;
                    int h  = n >> 6, dh0 = n & 63;
                    float x1 = acc[mt][nt][(half << 1) + 0];
                    float x2 = acc[mt][nt][(half << 1) + 1];
                    float* o = dst + ((size_t)((b << 4) + h) * S_LEN + sidx) * DH + dh0;
                    if (mode == 1) {
                        float2 cs = g_rope[sidx * (DH / 2) + (dh0 >> 1)];
                        o[0] = x1 * cs.x - x2 * cs.y;
                        o[1] = x1 * cs.y + x2 * cs.x;
                    } else {
                        o[0] = x1;
                        o[1] = x2;
                    }
                }
            }
        }
    }
}

__global__ __launch_bounds__(256) void gemm_mma_qkv(const __nv_bfloat16* __restrict__ xh,
                                                    const __nv_bfloat16* __restrict__ xl,
                                                    const __nv_bfloat16* __restrict__ wh,
                                                    const __nv_bfloat16* __restrict__ wl,
                                                    float* dq, float* dk, float* dv) {
    const int z = blockIdx.z;
    float* d = (z == 0) ? dq : (z == 1) ? dk : dv;
    gemm_mma_body(xh, xl, wh + (size_t)z * DM * DM, wl + (size_t)z * DM * DM,
                  d, (z == 2) ? 0 : 1);
}

__global__ __launch_bounds__(256) void gemm_mma_out(const __nv_bfloat16* __restrict__ ah,
                                                    const __nv_bfloat16* __restrict__ al,
                                                    const __nv_bfloat16* __restrict__ wh,
                                                    const __nv_bfloat16* __restrict__ wl,
                                                    float* dst) {
    gemm_mma_body(ah, al, wh, wl, dst, 2);
}

// ----------------------------------------------------------------------------
// Causal flash attention, fp32, f32x2 FMA (unchanged — passing at ~420us).
// ----------------------------------------------------------------------------
__global__ __launch_bounds__(256) void attn_kernel(const float* __restrict__ Q,
                                                   const float* __restrict__ K,
                                                   const float* __restrict__ V,
                                                   float* __restrict__ O) {
    __shared__ __align__(16) float Qs[64][64];
    __shared__ __align__(16) float Ks[64][64];   // aliased as P after scores
    __shared__ __align__(16) float Vs[64 * 64];  // swizzled

    const int tid = threadIdx.x;
    const int tx = tid & 15, ty = tid >> 4;
    const int bh = (int)blockIdx.x;
    const int qt = 31 - (int)blockIdx.y;         // heavy tiles first
    const int q0 = qt << 6;
    const float* qb = Q + ((size_t)bh * S_LEN + q0) * DH;

#pragma unroll
    for (int r = 0; r < 4; r++) {
        int t = tid + (r << 8);
        int row = t & 63, c4 = t >> 6;
        float4 vq = *(const float4*)(qb + row * DH + (c4 << 2));
        Qs[(c4 << 2) + 0][row] = vq.x; Qs[(c4 << 2) + 1][row] = vq.y;
        Qs[(c4 << 2) + 2][row] = vq.z; Qs[(c4 << 2) + 3][row] = vq.w;
    }

    unsigned long long op[4][2];
    float mrun[4], lrun[4];
#pragma unroll
    for (int i = 0; i < 4; i++) {
        op[i][0] = 0ull; op[i][1] = 0ull;
        mrun[i] = -1e30f; lrun[i] = 0.0f;
    }

    const float L2E = 1.4426950408889634f;

    for (int jt = 0; jt <= qt; ++jt) {
        const int k0 = jt << 6;
        const float* kb = K + ((size_t)bh * S_LEN + k0) * DH;
        const float* vb = V + ((size_t)bh * S_LEN + k0) * DH;

        __syncthreads();
#pragma unroll
        for (int r = 0; r < 4; r++) {
            int t = tid + (r << 8);
            int row = t & 63, c4 = t >> 6;
            float4 kv = *(const float4*)(kb + row * DH + (c4 << 2));
            Ks[(c4 << 2) + 0][row] = kv.x; Ks[(c4 << 2) + 1][row] = kv.y;
            Ks[(c4 << 2) + 2][row] = kv.z; Ks[(c4 << 2) + 3][row] = kv.w;
            float4 vv = *(const float4*)(vb + row * DH + (c4 << 2));
            *(float4*)&Vs[(row << 6) + ((c4 ^ (row & 15)) << 2)] = vv;
        }
        __syncthreads();

        unsigned long long sp[4][2];
#pragma unroll
        for (int i = 0; i < 4; i++) { sp[i][0] = 0ull; sp[i][1] = 0ull; }
#pragma unroll 8
        for (int k = 0; k < 64; k++) {
            float4  a  = *(const float4*)&Qs[k][ty << 2];
            double2 kk = *(const double2*)&Ks[k][tx << 2];
            unsigned long long b0 = dbits(kk.x), b1 = dbits(kk.y), ad;
            PACKDUP(ad, a.x); FFMA2(sp[0][0], ad, b0); FFMA2(sp[0][1], ad, b1);
            PACKDUP(ad, a.y); FFMA2(sp[1][0], ad, b0); FFMA2(sp[1][1], ad, b1);
            PACKDUP(ad, a.z); FFMA2(sp[2][0], ad, b0); FFMA2(sp[2][1], ad, b1);
            PACKDUP(ad, a.w); FFMA2(sp[3][0], ad, b0); FFMA2(sp[3][1], ad, b1);
        }
        __syncthreads();

        float* Ps = &Ks[0][0];
#pragma unroll
        for (int i = 0; i < 4; i++) {
            float s0 = lo2(sp[i][0]) * 0.125f;
            float s1 = hi2(sp[i][0]) * 0.125f;
            float s2 = lo2(sp[i][1]) * 0.125f;
            float s3 = hi2(sp[i][1]) * 0.125f;
            if (jt == qt) {
                int rl = (ty << 2) + i, cl = tx << 2;
                if (cl + 0 > rl) s0 = -1e30f;
                if (cl + 1 > rl) s1 = -1e30f;
                if (cl + 2 > rl) s2 = -1e30f;
                if (cl + 3 > rl) s3 = -1e30f;
            }
            float mt = fmaxf(fmaxf(s0, s1), fmaxf(s2, s3));
#pragma unroll
            for (int w = 8; w >= 1; w >>= 1)
                mt = fmaxf(mt, __shfl_xor_sync(0xffffffffu, mt, w));
            float mnew = fmaxf(mrun[i], mt);
            float al = exp2f((mrun[i] - mnew) * L2E);
            mrun[i] = mnew;
            float p0 = exp2f((s0 - mnew) * L2E);
            float p1 = exp2f((s1 - mnew) * L2E);
            float p2 = exp2f((s2 - mnew) * L2E);
            float p3 = exp2f((s3 - mnew) * L2E);
            float rs = (p0 + p1) + (p2 + p3);
#pragma unroll
            for (int w = 8; w >= 1; w >>= 1)
                rs += __shfl_xor_sync(0xffffffffu, rs, w);
            lrun[i] = lrun[i] * al + rs;
            unsigned long long alp;
            PACKDUP(alp, al);
            SCALE2(op[i][0], alp);
            SCALE2(op[i][1], alp);
            *(float4*)&Ps[(((ty << 2) + i) << 6) + (tx << 2)] =
                make_float4(p0, p1, p2, p3);
        }
        __syncthreads();

#pragma unroll 4
        for (int k4 = 0; k4 < 64; k4 += 4) {
            float4 pr[4];
#pragma unroll
            for (int i = 0; i < 4; i++)
                pr[i] = *(const float4*)&Ps[(((ty << 2) + i) << 6) + k4];
#pragma unroll
            for (int kk = 0; kk < 4; kk++) {
                int krow = k4 + kk;
                double2 vv = *(const double2*)
                    &Vs[(krow << 6) + ((tx ^ (krow & 15)) << 2)];
                unsigned long long v0 = dbits(vv.x), v1 = dbits(vv.y), pd;
                PACKDUP(pd, ((const float*)&pr[0])[kk]);
                FFMA2(op[0][0], pd, v0); FFMA2(op[0][1], pd, v1);
                PACKDUP(pd, ((const float*)&pr[1])[kk]);
                FFMA2(op[1][0], pd, v0); FFMA2(op[1][1], pd, v1);
                PACKDUP(pd, ((const float*)&pr[2])[kk]);
                FFMA2(op[2][0], pd, v0); FFMA2(op[2][1], pd, v1);
                PACKDUP(pd, ((const float*)&pr[3])[kk]);
                FFMA2(op[3][0], pd, v0); FFMA2(op[3][1], pd, v1);
            }
        }
    }

    const int b = bh >> 4, h = bh & 15;
#pragma unroll
    for (int i = 0; i < 4; i++) {
        float inv = 1.0f / lrun[i];
        int srow = q0 + (ty << 2) + i;
        float* o = O + ((size_t)(b * S_LEN + srow)) * DM + (h << 6) + (tx << 2);
        o[0] = lo2(op[i][0]) * inv;
        o[1] = hi2(op[i][0]) * inv;
        o[2] = lo2(op[i][1]) * inv;
        o[3] = hi2(op[i][1]) * inv;
    }
}

// ----------------------------------------------------------------------------
// Launch
// ----------------------------------------------------------------------------
extern "C" void kernel_launch(void* const* d_in, const int* in_sizes, int n_in,
                              void* d_out, int out_size) {
    (void)in_sizes; (void)n_in; (void)out_size;
    const float* X  = (const float*)d_in[0];
    const float* Wq = (const float*)d_in[1];
    const float* Wk = (const float*)d_in[2];
    const float* Wv = (const float*)d_in[3];
    const float* Wo = (const float*)d_in[4];
    float* out = (float*)d_out;

    float *gq, *gk, *gv, *ga;
    float2* grope;
    __nv_bfloat16 *xh, *xl, *wh, *wl;
    cudaGetSymbolAddress((void**)&gq, g_q);
    cudaGetSymbolAddress((void**)&gk, g_k);
    cudaGetSymbolAddress((void**)&gv, g_v);
    cudaGetSymbolAddress((void**)&ga, g_attn);
    cudaGetSymbolAddress((void**)&grope, g_rope);
    cudaGetSymbolAddress((void**)&xh, g_xh);
    cudaGetSymbolAddress((void**)&xl, g_xl);
    cudaGetSymbolAddress((void**)&wh, g_wh);
    cudaGetSymbolAddress((void**)&wl, g_wl);

    cudaFuncSetAttribute(gemm_mma_qkv, cudaFuncAttributeMaxDynamicSharedMemorySize, GSMEM_SZ);
    cudaFuncSetAttribute(gemm_mma_out, cudaFuncAttributeMaxDynamicSharedMemorySize, GSMEM_SZ);

    rope_table_kernel<<<256, 256>>>(grope);

    // bf16 hi/lo splits: input + 4 weight matrices
    split_kernel<<<(MROWS * DM / 4 + 255) / 256, 256>>>(X, xh, xl, MROWS * DM / 4);
    split_kernel<<<(DM * DM / 4 + 255) / 256, 256>>>(Wq, wh + 0 * (size_t)DM * DM, wl + 0 * (size_t)DM * DM, DM * DM / 4);
    split_kernel<<<(DM * DM / 4 + 255) / 256, 256>>>(Wk, wh + 1 * (size_t)DM * DM, wl + 1 * (size_t)DM * DM, DM * DM / 4);
    split_kernel<<<(DM * DM / 4 + 255) / 256, 256>>>(Wv, wh + 2 * (size_t)DM * DM, wl + 2 * (size_t)DM * DM, DM * DM / 4);
    split_kernel<<<(DM * DM / 4 + 255) / 256, 256>>>(Wo, wh + 3 * (size_t)DM * DM, wl + 3 * (size_t)DM * DM, DM * DM / 4);

    // QKV projections on tensor cores (grid.z = q/k/v)
    gemm_mma_qkv<<<dim3(DM / 128, MROWS / 128, 3), 256, GSMEM_SZ>>>(
        xh, xl, wh, wl, gq, gk, gv);

    attn_kernel<<<dim3(BATCH * NH, S_LEN / 64), 256>>>(gq, gk, gv, ga);

    // split attention output, then output projection on tensor cores
    split_kernel<<<(MROWS * DM / 4 + 255) / 256, 256>>>(ga, xh, xl, MROWS * DM / 4);
    gemm_mma_out<<<dim3(DM / 128, MROWS / 128), 256, GSMEM_SZ>>>(
        xh, xl, wh + 3 * (size_t)DM * DM, wl + 3 * (size_t)DM * DM, out);
}

// round 15
// speedup vs baseline: 3.7433x; 1.7514x over previous
#include <cuda_runtime.h>
#include <cuda_bf16.h>
#include <math.h>
#include <stdint.h>

// ----------------------------------------------------------------------------
// Problem constants
// ----------------------------------------------------------------------------
#define S_LEN 2048
#define BATCH 2
#define DM    1024
#define NH    16
#define DH    64
#define MROWS (BATCH * S_LEN)   // 4096

// ----------------------------------------------------------------------------
// Scratch (static device globals: allocation inside kernel_launch is banned)
// ----------------------------------------------------------------------------
__device__ float2 g_rope[S_LEN * (DH / 2)];         // (cos, sin) per (s, freq)

// bf16 hi/lo splits
__device__ __align__(16) __nv_bfloat16 g_xh[MROWS * DM];
__device__ __align__(16) __nv_bfloat16 g_xl[MROWS * DM];
__device__ __align__(16) __nv_bfloat16 g_wh[4 * DM * DM];   // Wq,Wk,Wv,Wo hi
__device__ __align__(16) __nv_bfloat16 g_wl[4 * DM * DM];   // Wq,Wk,Wv,Wo lo
// rope'd Q/K and V, bf16 hi/lo, layout [bh][s][dh]
__device__ __align__(16) __nv_bfloat16 g_qh[BATCH * NH * S_LEN * DH];
__device__ __align__(16) __nv_bfloat16 g_ql[BATCH * NH * S_LEN * DH];
__device__ __align__(16) __nv_bfloat16 g_kh[BATCH * NH * S_LEN * DH];
__device__ __align__(16) __nv_bfloat16 g_kl[BATCH * NH * S_LEN * DH];
__device__ __align__(16) __nv_bfloat16 g_vh[BATCH * NH * S_LEN * DH];
__device__ __align__(16) __nv_bfloat16 g_vl[BATCH * NH * S_LEN * DH];

// ----------------------------------------------------------------------------
// mma.sync / ldmatrix / cp.async helpers (all sm_80+ PTX; ok on compute_103)
// ----------------------------------------------------------------------------
__device__ __forceinline__ uint32_t smem_u32(const void* p) {
    uint32_t a;
    asm("{ .reg .u64 t; cvta.to.shared.u64 t, %1; cvt.u32.u64 %0, t; }" : "=r"(a) : "l"(p));
    return a;
}
__device__ __forceinline__ void ldsm4(uint32_t (&r)[4], uint32_t addr) {
    asm volatile("ldmatrix.sync.aligned.m8n8.x4.shared.b16 {%0,%1,%2,%3}, [%4];"
                 : "=r"(r[0]), "=r"(r[1]), "=r"(r[2]), "=r"(r[3]) : "r"(addr));
}
__device__ __forceinline__ void ldsm4t(uint32_t (&r)[4], uint32_t addr) {
    asm volatile("ldmatrix.sync.aligned.m8n8.x4.trans.shared.b16 {%0,%1,%2,%3}, [%4];"
                 : "=r"(r[0]), "=r"(r[1]), "=r"(r[2]), "=r"(r[3]) : "r"(addr));
}
__device__ __forceinline__ void mma16816(float (&d)[4], const uint32_t (&a)[4],
                                         uint32_t b0, uint32_t b1) {
    asm volatile(
        "mma.sync.aligned.m16n8k16.row.col.f32.bf16.bf16.f32 "
        "{%0,%1,%2,%3}, {%4,%5,%6,%7}, {%8,%9}, {%0,%1,%2,%3};"
        : "+f"(d[0]), "+f"(d[1]), "+f"(d[2]), "+f"(d[3])
        : "r"(a[0]), "r"(a[1]), "r"(a[2]), "r"(a[3]), "r"(b0), "r"(b1));
}
#define CP16(dst, src) \
    asm volatile("cp.async.cg.shared.global [%0], [%1], 16;" :: "r"(dst), "l"(src))
#define CP_COMMIT() asm volatile("cp.async.commit_group;")
#define CP_WAIT1()  asm volatile("cp.async.wait_group 1;")
#define CP_WAIT0()  asm volatile("cp.async.wait_group 0;")

__device__ __forceinline__ uint32_t b2u(__nv_bfloat162 v) {
    uint32_t r; *(__nv_bfloat162*)&r = v; return r;
}

// ----------------------------------------------------------------------------
// RoPE table (fp32-rounded angle, double trig for exact range reduction)
// ----------------------------------------------------------------------------
__global__ void rope_table_kernel(float2* __restrict__ tab) {
    int idx = blockIdx.x * blockDim.x + threadIdx.x;
    if (idx >= S_LEN * (DH / 2)) return;
    int s = idx >> 5;
    int i = idx & 31;
    double e = (double)(2 * i) / (double)DH;
    float invf = (float)exp(-e * log(10000.0));
    float ang  = (float)s * invf;
    double a   = (double)ang;
    tab[idx] = make_float2((float)cos(a), (float)sin(a));
}

// ----------------------------------------------------------------------------
// bf16 hi/lo split: h = bf16(x), l = bf16(x - h)
// ----------------------------------------------------------------------------
__global__ void split_kernel(const float* __restrict__ x,
                             __nv_bfloat16* __restrict__ h,
                             __nv_bfloat16* __restrict__ l, int n4) {
    int i = blockIdx.x * blockDim.x + threadIdx.x;
    if (i >= n4) return;
    float4 v = ((const float4*)x)[i];
    float a[4] = {v.x, v.y, v.z, v.w};
    __nv_bfloat162 hh[2], ll[2];
#pragma unroll
    for (int j = 0; j < 2; j++) {
        __nv_bfloat16 h0 = __float2bfloat16(a[2 * j]);
        __nv_bfloat16 h1 = __float2bfloat16(a[2 * j + 1]);
        __nv_bfloat16 l0 = __float2bfloat16(a[2 * j] - __bfloat162float(h0));
        __nv_bfloat16 l1 = __float2bfloat16(a[2 * j + 1] - __bfloat162float(h1));
        hh[j].x = h0; hh[j].y = h1;
        ll[j].x = l0; ll[j].y = l1;
    }
    ((__nv_bfloat162*)h)[2 * i]     = hh[0];
    ((__nv_bfloat162*)h)[2 * i + 1] = hh[1];
    ((__nv_bfloat162*)l)[2 * i]     = ll[0];
    ((__nv_bfloat162*)l)[2 * i + 1] = ll[1];
}

// ----------------------------------------------------------------------------
// mma.sync NT GEMM (unchanged core from R14-pass).
// mode 0: V -> bf16 h/l scatter [bh][s][dh]
// mode 1: Q/K -> RoPE + bf16 h/l scatter
// mode 2: fp32 row-major (output projection)
// ----------------------------------------------------------------------------
#define GA0 0
#define GA1 16384
#define GB0 32768
#define GB1 49152
#define GSMEM_SZ 65536

__device__ __forceinline__ void gemm_mma_body(const __nv_bfloat16* __restrict__ Ah,
                                              const __nv_bfloat16* __restrict__ Al,
                                              const __nv_bfloat16* __restrict__ Bh,
                                              const __nv_bfloat16* __restrict__ Bl,
                                              float* __restrict__ dstf,
                                              __nv_bfloat16* __restrict__ dsth,
                                              __nv_bfloat16* __restrict__ dstl,
                                              int mode) {
    extern __shared__ char smem[];
    const uint32_t sb = smem_u32(smem);
    const int tid  = threadIdx.x;
    const int wid  = tid >> 5, lane = tid & 31;
    const int wm   = wid & 1;
    const int wn   = wid >> 1;
    const int m0 = (int)blockIdx.y << 7;
    const int n0 = (int)blockIdx.x << 7;

    const int r8  = tid >> 3;
    const int c16 = tid & 7;

    auto ldg_chunk = [&](int c, uint4 (&ra)[4], uint4 (&rb)[4]) {
        int seg = c >> 4, ko = (c & 15) << 6;
        const __nv_bfloat16* As = (seg == 1) ? Al : Ah;
        const __nv_bfloat16* Bs = (seg == 2) ? Bl : Bh;
#pragma unroll
        for (int r = 0; r < 4; r++) {
            int rr = (r << 5) + r8;
            ra[r] = *(const uint4*)(As + (size_t)(m0 + rr) * DM + ko + (c16 << 3));
            rb[r] = *(const uint4*)(Bs + (size_t)(n0 + rr) * DM + ko + (c16 << 3));
        }
    };
    auto sts_chunk = [&](uint32_t aofs, uint32_t bofs,
                         const uint4 (&ra)[4], const uint4 (&rb)[4]) {
#pragma unroll
        for (int r = 0; r < 4; r++) {
            int rr = (r << 5) + r8;
            uint32_t off = (rr << 7) + ((c16 << 4) ^ ((rr & 7) << 4));
            *(uint4*)(smem + aofs + off) = ra[r];
            *(uint4*)(smem + bofs + off) = rb[r];
        }
    };

    uint32_t aoff[4][4], boff[2][4];
    {
        int arow = (wm << 6) + (((lane >> 3) & 1) << 3) + (lane & 7);
        int akb  = ((lane >> 4) & 1) << 4;
        int brow = (wn << 5) + (((lane >> 4) & 1) << 3) + (lane & 7);
        int bkb  = ((lane >> 3) & 1) << 4;
#pragma unroll
        for (int kk = 0; kk < 4; kk++) {
#pragma unroll
            for (int mt = 0; mt < 4; mt++) {
                int row = arow + (mt << 4);
                aoff[mt][kk] = (row << 7) + (((kk << 5) + akb) ^ ((row & 7) << 4));
            }
#pragma unroll
            for (int nb = 0; nb < 2; nb++) {
                int row = brow + (nb << 4);
                boff[nb][kk] = (row << 7) + (((kk << 5) + bkb) ^ ((row & 7) << 4));
            }
        }
    }

    float acc[4][4][4];
#pragma unroll
    for (int i = 0; i < 4; i++)
#pragma unroll
        for (int j = 0; j < 4; j++)
#pragma unroll
            for (int t = 0; t < 4; t++) acc[i][j][t] = 0.0f;

    {
        uint4 ra[4], rb[4];
        ldg_chunk(0, ra, rb);
        sts_chunk(GA0, GB0, ra, rb);
    }
    __syncthreads();

    for (int c = 0; c < 48; c++) {
        const int s = c & 1;
        const uint32_t abase = sb + (s ? GA1 : GA0);
        const uint32_t bbase = sb + (s ? GB1 : GB0);
        uint4 ra[4], rb[4];
        const bool more = (c < 47);
        if (more) ldg_chunk(c + 1, ra, rb);

#pragma unroll
        for (int kk = 0; kk < 4; kk++) {
            uint32_t af[4][4], bf[2][4];
#pragma unroll
            for (int mt = 0; mt < 4; mt++) ldsm4(af[mt], abase + aoff[mt][kk]);
#pragma unroll
            for (int nb = 0; nb < 2; nb++) ldsm4(bf[nb], bbase + boff[nb][kk]);
#pragma unroll
            for (int mt = 0; mt < 4; mt++)
#pragma unroll
                for (int nt = 0; nt < 4; nt++)
                    mma16816(acc[mt][nt], af[mt],
                             bf[nt >> 1][(nt & 1) << 1],
                             bf[nt >> 1][((nt & 1) << 1) + 1]);
        }
        if (more) sts_chunk(s ? GA0 : GA1, s ? GB0 : GB1, ra, rb);
        __syncthreads();
    }

    const int er = (lane >> 2);
    const int ec = (lane & 3) << 1;
#pragma unroll
    for (int mt = 0; mt < 4; mt++) {
#pragma unroll
        for (int half = 0; half < 2; half++) {
            int m = m0 + (wm << 6) + (mt << 4) + (half << 3) + er;
            if (mode == 2) {
                float* o = dstf + (size_t)m * DM + n0 + (wn << 5) + ec;
#pragma unroll
                for (int nt = 0; nt < 4; nt++) {
                    o[(nt << 3) + 0] = acc[mt][nt][(half << 1) + 0];
                    o[(nt << 3) + 1] = acc[mt][nt][(half << 1) + 1];
                }
            } else {
                const int b = m >> 11, sidx = m & (S_LEN - 1);
#pragma unroll
                for (int nt = 0; nt < 4; nt++) {
                    int n  = n0 + (wn << 5) + (nt << 3) + ec;
                    int h  = n >> 6, dh0 = n & 63;
                    float x1 = acc[mt][nt][(half << 1) + 0];
                    float x2 = acc[mt][nt][(half << 1) + 1];
                    if (mode == 1) {
                        float2 cs = g_rope[sidx * (DH / 2) + (dh0 >> 1)];
                        float y1 = x1 * cs.x - x2 * cs.y;
                        float y2 = x1 * cs.y + x2 * cs.x;
                        x1 = y1; x2 = y2;
                    }
                    size_t off = ((size_t)((b << 4) + h) * S_LEN + sidx) * DH + dh0;
                    __nv_bfloat162 hh = __floats2bfloat162_rn(x1, x2);
                    __nv_bfloat162 ll = __floats2bfloat162_rn(
                        x1 - __low2float(hh), x2 - __high2float(hh));
                    *(__nv_bfloat162*)(dsth + off) = hh;
                    *(__nv_bfloat162*)(dstl + off) = ll;
                }
            }
        }
    }
}

__global__ __launch_bounds__(256) void gemm_mma_qkv(const __nv_bfloat16* __restrict__ xh,
                                                    const __nv_bfloat16* __restrict__ xl,
                                                    const __nv_bfloat16* __restrict__ wh,
                                                    const __nv_bfloat16* __restrict__ wl,
                                                    __nv_bfloat16* qh, __nv_bfloat16* ql,
                                                    __nv_bfloat16* kh, __nv_bfloat16* kl,
                                                    __nv_bfloat16* vh, __nv_bfloat16* vl) {
    const int z = blockIdx.z;
    __nv_bfloat16* dh_ = (z == 0) ? qh : (z == 1) ? kh : vh;
    __nv_bfloat16* dl_ = (z == 0) ? ql : (z == 1) ? kl : vl;
    gemm_mma_body(xh, xl, wh + (size_t)z * DM * DM, wl + (size_t)z * DM * DM,
                  nullptr, dh_, dl_, (z == 2) ? 0 : 1);
}

__global__ __launch_bounds__(256) void gemm_mma_out(const __nv_bfloat16* __restrict__ ah,
                                                    const __nv_bfloat16* __restrict__ al,
                                                    const __nv_bfloat16* __restrict__ wh,
                                                    const __nv_bfloat16* __restrict__ wl,
                                                    float* dst) {
    gemm_mma_body(ah, al, wh, wl, dst, nullptr, nullptr, 2);
}

// ----------------------------------------------------------------------------
// Tensor-core causal flash attention, bf16 hi/lo split, fp32 accum.
// Block: 128 q-rows, 8 warps (16 rows each). KV tiles of 64 keys,
// cp.async double-buffered. Softmax fully warp-local.
// Smem: Q (h+l) 32KB at 0; KV buffers 32KB each at 32K/64K
//       (per buffer: Kh 0, Kl 8K, Vh 16K, Vl 24K).
// ----------------------------------------------------------------------------
#define ATB0 32768
#define ATB1 65536
#define ATK_H 0
#define ATK_L 8192
#define ATV_H 16384
#define ATV_L 24576
#define ASMEM_SZ 98304
#define SCL2E 0.18033688011112042f   // 0.125 * log2(e)

__global__ __launch_bounds__(256) void attn_mma(
    const __nv_bfloat16* __restrict__ qh, const __nv_bfloat16* __restrict__ ql,
    const __nv_bfloat16* __restrict__ kh, const __nv_bfloat16* __restrict__ kl,
    const __nv_bfloat16* __restrict__ vh, const __nv_bfloat16* __restrict__ vl,
    __nv_bfloat16* __restrict__ oh, __nv_bfloat16* __restrict__ ol) {
    extern __shared__ char smem[];
    const uint32_t sb = smem_u32(smem);
    const int tid = threadIdx.x, wid = tid >> 5, lane = tid & 31;
    const int bh = (int)blockIdx.x;
    const int t  = 15 - (int)blockIdx.y;      // heavy tiles first
    const int q0 = t << 7;
    const int ntile = 2 * t + 2;
    const size_t base = (size_t)bh * S_LEN * DH;

    const int r8 = tid >> 3, c16 = tid & 7;
    const uint32_t stc = (uint32_t)(c16 << 4);

    // ---- prolog: Q (h+l) + KV tile 0 via cp.async, one group ----
#pragma unroll
    for (int k = 0; k < 4; k++) {
        int row = (k << 5) + r8;
        uint32_t d = sb + (row << 7) + (stc ^ ((row & 7) << 4));
        const size_t g = base + (size_t)(q0 + row) * DH + (c16 << 3);
        CP16(d,         (const char*)(qh + g));
        CP16(d + 16384, (const char*)(ql + g));
    }
    auto kv_load = [&](int jt, uint32_t bufofs) {
        int k0 = jt << 6;
#pragma unroll
        for (int r = 0; r < 2; r++) {
            int row = (r << 5) + r8;
            uint32_t d = sb + bufofs + (row << 7) + (stc ^ ((row & 7) << 4));
            const size_t g = base + (size_t)(k0 + row) * DH + (c16 << 3);
            CP16(d + ATK_H, (const char*)(kh + g));
            CP16(d + ATK_L, (const char*)(kl + g));
            CP16(d + ATV_H, (const char*)(vh + g));
            CP16(d + ATV_L, (const char*)(vl + g));
        }
    };
    kv_load(0, ATB0);
    CP_COMMIT();

    // ---- fragment address components ----
    const uint32_t swz = (uint32_t)((lane & 7) << 4);
    const uint32_t qrow = (uint32_t)(((wid << 4) + (((lane >> 3) & 1) << 3) + (lane & 7)) << 7);
    const uint32_t akb  = (uint32_t)(((lane >> 4) & 1) << 4);
    const int brow = (((lane >> 4) & 1) << 3) + (lane & 7);
    const uint32_t bkb = (uint32_t)(((lane >> 3) & 1) << 4);
    const int vrow = (((lane >> 3) & 1) << 3) + (lane & 7);
    const uint32_t vnb = (uint32_t)(((lane >> 4) & 1) << 4);

    float O[8][4];
#pragma unroll
    for (int i = 0; i < 8; i++) { O[i][0] = O[i][1] = O[i][2] = O[i][3] = 0.f; }
    float mr0 = -1e30f, mr1 = -1e30f, lr0 = 0.f, lr1 = 0.f;
    const int row0 = q0 + (wid << 4) + (lane >> 2);

    for (int jt = 0; jt < ntile; jt++) {
        const bool more = (jt + 1 < ntile);
        if (more) { kv_load(jt + 1, (jt & 1) ? ATB0 : ATB1); CP_COMMIT(); }
        if (more) { CP_WAIT1(); } else { CP_WAIT0(); }
        __syncthreads();
        const uint32_t bufb = sb + ((jt & 1) ? ATB1 : ATB0);

        // ---- S = Q K^T  (QhKh + QlKh + QhKl) ----
        float S[8][4];
#pragma unroll
        for (int i = 0; i < 8; i++) { S[i][0] = S[i][1] = S[i][2] = S[i][3] = 0.f; }
#pragma unroll
        for (int kc = 0; kc < 4; kc++) {
            uint32_t qo = sb + qrow + ((((uint32_t)(kc << 5)) | akb) ^ swz);
            uint32_t ah4[4], al4[4];
            ldsm4(ah4, qo);
            ldsm4(al4, qo + 16384);
#pragma unroll
            for (int np = 0; np < 4; np++) {
                uint32_t ko = bufb + (uint32_t)((((np << 4) + brow) << 7)) +
                              ((((uint32_t)(kc << 5)) | bkb) ^ swz);
                uint32_t kf[4];
                ldsm4(kf, ko + ATK_H);
                mma16816(S[2 * np],     ah4, kf[0], kf[1]);
                mma16816(S[2 * np + 1], ah4, kf[2], kf[3]);
                mma16816(S[2 * np],     al4, kf[0], kf[1]);
                mma16816(S[2 * np + 1], al4, kf[2], kf[3]);
                ldsm4(kf, ko + ATK_L);
                mma16816(S[2 * np],     ah4, kf[0], kf[1]);
                mma16816(S[2 * np + 1], ah4, kf[2], kf[3]);
            }
        }

        // ---- online softmax (warp-local) ----
        const bool msk = (jt >= 2 * t);
        const int kbase = (jt << 6) + ((lane & 3) << 1);
        float m0 = -1e30f, m1 = -1e30f;
#pragma unroll
        for (int nt = 0; nt < 8; nt++) {
            float v0 = S[nt][0] * SCL2E, v1 = S[nt][1] * SCL2E;
            float v2 = S[nt][2] * SCL2E, v3 = S[nt][3] * SCL2E;
            if (msk) {
                int kc0 = kbase + (nt << 3);
                if (kc0     > row0)     v0 = -1e30f;
                if (kc0 + 1 > row0)     v1 = -1e30f;
                if (kc0     > row0 + 8) v2 = -1e30f;
                if (kc0 + 1 > row0 + 8) v3 = -1e30f;
            }
            S[nt][0] = v0; S[nt][1] = v1; S[nt][2] = v2; S[nt][3] = v3;
            m0 = fmaxf(m0, fmaxf(v0, v1));
            m1 = fmaxf(m1, fmaxf(v2, v3));
        }
        m0 = fmaxf(m0, __shfl_xor_sync(0xffffffffu, m0, 1));
        m0 = fmaxf(m0, __shfl_xor_sync(0xffffffffu, m0, 2));
        m1 = fmaxf(m1, __shfl_xor_sync(0xffffffffu, m1, 1));
        m1 = fmaxf(m1, __shfl_xor_sync(0xffffffffu, m1, 2));
        float mn0 = fmaxf(mr0, m0), mn1 = fmaxf(mr1, m1);
        float a0 = exp2f(mr0 - mn0), a1 = exp2f(mr1 - mn1);
        mr0 = mn0; mr1 = mn1;

        float s0 = 0.f, s1 = 0.f;
        uint32_t php[8][2], plp[8][2];
#pragma unroll
        for (int nt = 0; nt < 8; nt++) {
            float p0 = exp2f(S[nt][0] - mn0), p1 = exp2f(S[nt][1] - mn0);
            float p2 = exp2f(S[nt][2] - mn1), p3 = exp2f(S[nt][3] - mn1);
            s0 += p0 + p1; s1 += p2 + p3;
            __nv_bfloat162 h01 = __floats2bfloat162_rn(p0, p1);
            __nv_bfloat162 h23 = __floats2bfloat162_rn(p2, p3);
            php[nt][0] = b2u(h01); php[nt][1] = b2u(h23);
            __nv_bfloat162 l01 = __floats2bfloat162_rn(p0 - __low2float(h01),
                                                       p1 - __high2float(h01));
            __nv_bfloat162 l23 = __floats2bfloat162_rn(p2 - __low2float(h23),
                                                       p3 - __high2float(h23));
            plp[nt][0] = b2u(l01); plp[nt][1] = b2u(l23);
            O[nt][0] *= a0; O[nt][1] *= a0; O[nt][2] *= a1; O[nt][3] *= a1;
        }
        s0 += __shfl_xor_sync(0xffffffffu, s0, 1);
        s0 += __shfl_xor_sync(0xffffffffu, s0, 2);
        s1 += __shfl_xor_sync(0xffffffffu, s1, 1);
        s1 += __shfl_xor_sync(0xffffffffu, s1, 2);
        lr0 = lr0 * a0 + s0;
        lr1 = lr1 * a1 + s1;

        // ---- O += P V  (PhVh + PlVh + PhVl);  V via ldmatrix.trans ----
#pragma unroll
        for (int kc = 0; kc < 4; kc++) {
            uint32_t pah[4] = { php[2 * kc][0], php[2 * kc][1],
                                php[2 * kc + 1][0], php[2 * kc + 1][1] };
            uint32_t pal[4] = { plp[2 * kc][0], plp[2 * kc][1],
                                plp[2 * kc + 1][0], plp[2 * kc + 1][1] };
#pragma unroll
            for (int nv = 0; nv < 4; nv++) {
                uint32_t vo = bufb + (uint32_t)((((kc << 4) + vrow) << 7)) +
                              ((((uint32_t)(nv << 5)) | vnb) ^ swz);
                uint32_t vf[4];
                ldsm4t(vf, vo + ATV_H);
                mma16816(O[2 * nv],     pah, vf[0], vf[1]);
                mma16816(O[2 * nv + 1], pah, vf[2], vf[3]);
                mma16816(O[2 * nv],     pal, vf[0], vf[1]);
                mma16816(O[2 * nv + 1], pal, vf[2], vf[3]);
                ldsm4t(vf, vo + ATV_L);
                mma16816(O[2 * nv],     pah, vf[0], vf[1]);
                mma16816(O[2 * nv + 1], pah, vf[2], vf[3]);
            }
        }
        __syncthreads();
    }

    // ---- epilogue: normalize + write bf16 hi/lo splits [m][h*64+dh] ----
    const float i0 = 1.0f / lr0, i1 = 1.0f / lr1;
    const int b = bh >> 4, h = bh & 15;
    const int gr0 = q0 + (wid << 4) + (lane >> 2);
    const size_t ro0 = ((size_t)(b * S_LEN + gr0)) * DM + (h << 6);
    const size_t ro1 = ro0 + (size_t)8 * DM;
#pragma unroll
    for (int nt = 0; nt < 8; nt++) {
        int dh0 = (nt << 3) + ((lane & 3) << 1);
        float y0 = O[nt][0] * i0, y1 = O[nt][1] * i0;
        float y2 = O[nt][2] * i1, y3 = O[nt][3] * i1;
        __nv_bfloat162 h01 = __floats2bfloat162_rn(y0, y1);
        __nv_bfloat162 l01 = __floats2bfloat162_rn(y0 - __low2float(h01),
                                                   y1 - __high2float(h01));
        *(__nv_bfloat162*)(oh + ro0 + dh0) = h01;
        *(__nv_bfloat162*)(ol + ro0 + dh0) = l01;
        __nv_bfloat162 h23 = __floats2bfloat162_rn(y2, y3);
        __nv_bfloat162 l23 = __floats2bfloat162_rn(y2 - __low2float(h23),
                                                   y3 - __high2float(h23));
        *(__nv_bfloat162*)(oh + ro1 + dh0) = h23;
        *(__nv_bfloat162*)(ol + ro1 + dh0) = l23;
    }
}

// ----------------------------------------------------------------------------
// Launch
// ----------------------------------------------------------------------------
extern "C" void kernel_launch(void* const* d_in, const int* in_sizes, int n_in,
                              void* d_out, int out_size) {
    (void)in_sizes; (void)n_in; (void)out_size;
    const float* X  = (const float*)d_in[0];
    const float* Wq = (const float*)d_in[1];
    const float* Wk = (const float*)d_in[2];
    const float* Wv = (const float*)d_in[3];
    const float* Wo = (const float*)d_in[4];
    float* out = (float*)d_out;

    float2* grope;
    __nv_bfloat16 *xh, *xl, *wh, *wl, *qh, *ql, *kh, *kl, *vh, *vl;
    cudaGetSymbolAddress((void**)&grope, g_rope);
    cudaGetSymbolAddress((void**)&xh, g_xh);
    cudaGetSymbolAddress((void**)&xl, g_xl);
    cudaGetSymbolAddress((void**)&wh, g_wh);
    cudaGetSymbolAddress((void**)&wl, g_wl);
    cudaGetSymbolAddress((void**)&qh, g_qh);
    cudaGetSymbolAddress((void**)&ql, g_ql);
    cudaGetSymbolAddress((void**)&kh, g_kh);
    cudaGetSymbolAddress((void**)&kl, g_kl);
    cudaGetSymbolAddress((void**)&vh, g_vh);
    cudaGetSymbolAddress((void**)&vl, g_vl);

    cudaFuncSetAttribute(gemm_mma_qkv, cudaFuncAttributeMaxDynamicSharedMemorySize, GSMEM_SZ);
    cudaFuncSetAttribute(gemm_mma_out, cudaFuncAttributeMaxDynamicSharedMemorySize, GSMEM_SZ);
    cudaFuncSetAttribute(attn_mma,     cudaFuncAttributeMaxDynamicSharedMemorySize, ASMEM_SZ);

    rope_table_kernel<<<256, 256>>>(grope);

    // bf16 hi/lo splits: input + 4 weight matrices
    split_kernel<<<(MROWS * DM / 4 + 255) / 256, 256>>>(X, xh, xl, MROWS * DM / 4);
    split_kernel<<<(DM * DM / 4 + 255) / 256, 256>>>(Wq, wh + 0 * (size_t)DM * DM, wl + 0 * (size_t)DM * DM, DM * DM / 4);
    split_kernel<<<(DM * DM / 4 + 255) / 256, 256>>>(Wk, wh + 1 * (size_t)DM * DM, wl + 1 * (size_t)DM * DM, DM * DM / 4);
    split_kernel<<<(DM * DM / 4 + 255) / 256, 256>>>(Wv, wh + 2 * (size_t)DM * DM, wl + 2 * (size_t)DM * DM, DM * DM / 4);
    split_kernel<<<(DM * DM / 4 + 255) / 256, 256>>>(Wo, wh + 3 * (size_t)DM * DM, wl + 3 * (size_t)DM * DM, DM * DM / 4);

    // QKV projections (epilogue applies RoPE + writes bf16 hi/lo splits)
    gemm_mma_qkv<<<dim3(DM / 128, MROWS / 128, 3), 256, GSMEM_SZ>>>(
        xh, xl, wh, wl, qh, ql, kh, kl, vh, vl);

    // tensor-core flash attention -> writes splits straight into xh/xl
    attn_mma<<<dim3(BATCH * NH, S_LEN / 128), 256, ASMEM_SZ>>>(
        qh, ql, kh, kl, vh, vl, xh, xl);

    // output projection
    gemm_mma_out<<<dim3(DM / 128, MROWS / 128), 256, GSMEM_SZ>>>(
        xh, xl, wh + 3 * (size_t)DM * DM, wl + 3 * (size_t)DM * DM, out);
}

// round 17
// speedup vs baseline: 4.3633x; 1.1657x over previous
#include <cuda_runtime.h>
#include <cuda_bf16.h>
#include <math.h>
#include <stdint.h>

// ----------------------------------------------------------------------------
// Problem constants
// ----------------------------------------------------------------------------
#define S_LEN 2048
#define BATCH 2
#define DM    1024
#define NH    16
#define DH    64
#define MROWS (BATCH * S_LEN)   // 4096

// ----------------------------------------------------------------------------
// Scratch (static device globals: allocation inside kernel_launch is banned)
// ----------------------------------------------------------------------------
__device__ float2 g_rope[S_LEN * (DH / 2)];         // (cos, sin) per (s, freq)

// bf16 hi/lo splits
__device__ __align__(16) __nv_bfloat16 g_xh[MROWS * DM];
__device__ __align__(16) __nv_bfloat16 g_xl[MROWS * DM];
__device__ __align__(16) __nv_bfloat16 g_wh[4 * DM * DM];   // Wq,Wk,Wv,Wo hi
__device__ __align__(16) __nv_bfloat16 g_wl[4 * DM * DM];   // Wq,Wk,Wv,Wo lo
// rope'd Q/K and V, bf16 hi/lo, layout [bh][s][dh]
__device__ __align__(16) __nv_bfloat16 g_qh[BATCH * NH * S_LEN * DH];
__device__ __align__(16) __nv_bfloat16 g_ql[BATCH * NH * S_LEN * DH];
__device__ __align__(16) __nv_bfloat16 g_kh[BATCH * NH * S_LEN * DH];
__device__ __align__(16) __nv_bfloat16 g_kl[BATCH * NH * S_LEN * DH];
__device__ __align__(16) __nv_bfloat16 g_vh[BATCH * NH * S_LEN * DH];
__device__ __align__(16) __nv_bfloat16 g_vl[BATCH * NH * S_LEN * DH];

// ----------------------------------------------------------------------------
// mma.sync / ldmatrix / cp.async helpers (all sm_80+ PTX; ok on compute_103)
// ----------------------------------------------------------------------------
__device__ __forceinline__ uint32_t smem_u32(const void* p) {
    uint32_t a;
    asm("{ .reg .u64 t; cvta.to.shared.u64 t, %1; cvt.u32.u64 %0, t; }" : "=r"(a) : "l"(p));
    return a;
}
__device__ __forceinline__ void ldsm4(uint32_t (&r)[4], uint32_t addr) {
    asm volatile("ldmatrix.sync.aligned.m8n8.x4.shared.b16 {%0,%1,%2,%3}, [%4];"
                 : "=r"(r[0]), "=r"(r[1]), "=r"(r[2]), "=r"(r[3]) : "r"(addr));
}
__device__ __forceinline__ void ldsm4t(uint32_t (&r)[4], uint32_t addr) {
    asm volatile("ldmatrix.sync.aligned.m8n8.x4.trans.shared.b16 {%0,%1,%2,%3}, [%4];"
                 : "=r"(r[0]), "=r"(r[1]), "=r"(r[2]), "=r"(r[3]) : "r"(addr));
}
__device__ __forceinline__ void mma16816(float (&d)[4], const uint32_t (&a)[4],
                                         uint32_t b0, uint32_t b1) {
    asm volatile(
        "mma.sync.aligned.m16n8k16.row.col.f32.bf16.bf16.f32 "
        "{%0,%1,%2,%3}, {%4,%5,%6,%7}, {%8,%9}, {%0,%1,%2,%3};"
        : "+f"(d[0]), "+f"(d[1]), "+f"(d[2]), "+f"(d[3])
        : "r"(a[0]), "r"(a[1]), "r"(a[2]), "r"(a[3]), "r"(b0), "r"(b1));
}
#define CP16(dst, src) \
    asm volatile("cp.async.cg.shared.global [%0], [%1], 16;" :: "r"(dst), "l"(src))
#define CP_COMMIT() asm volatile("cp.async.commit_group;")
#define CP_WAIT1()  asm volatile("cp.async.wait_group 1;")
#define CP_WAIT0()  asm volatile("cp.async.wait_group 0;")

__device__ __forceinline__ uint32_t b2u(__nv_bfloat162 v) {
    uint32_t r; *(__nv_bfloat162*)&r = v; return r;
}

// ----------------------------------------------------------------------------
// RoPE table (fp32-rounded angle, double trig for exact range reduction)
// ----------------------------------------------------------------------------
__global__ void rope_table_kernel(float2* __restrict__ tab) {
    int idx = blockIdx.x * blockDim.x + threadIdx.x;
    if (idx >= S_LEN * (DH / 2)) return;
    int s = idx >> 5;
    int i = idx & 31;
    double e = (double)(2 * i) / (double)DH;
    float invf = (float)exp(-e * log(10000.0));
    float ang  = (float)s * invf;
    double a   = (double)ang;
    tab[idx] = make_float2((float)cos(a), (float)sin(a));
}

// ----------------------------------------------------------------------------
// bf16 hi/lo split: h = bf16(x), l = bf16(x - h)
// ----------------------------------------------------------------------------
__global__ void split_kernel(const float* __restrict__ x,
                             __nv_bfloat16* __restrict__ h,
                             __nv_bfloat16* __restrict__ l, int n4) {
    int i = blockIdx.x * blockDim.x + threadIdx.x;
    if (i >= n4) return;
    float4 v = ((const float4*)x)[i];
    float a[4] = {v.x, v.y, v.z, v.w};
    __nv_bfloat162 hh[2], ll[2];
#pragma unroll
    for (int j = 0; j < 2; j++) {
        __nv_bfloat16 h0 = __float2bfloat16(a[2 * j]);
        __nv_bfloat16 h1 = __float2bfloat16(a[2 * j + 1]);
        __nv_bfloat16 l0 = __float2bfloat16(a[2 * j] - __bfloat162float(h0));
        __nv_bfloat16 l1 = __float2bfloat16(a[2 * j + 1] - __bfloat162float(h1));
        hh[j].x = h0; hh[j].y = h1;
        ll[j].x = l0; ll[j].y = l1;
    }
    ((__nv_bfloat162*)h)[2 * i]     = hh[0];
    ((__nv_bfloat162*)h)[2 * i + 1] = hh[1];
    ((__nv_bfloat162*)l)[2 * i]     = ll[0];
    ((__nv_bfloat162*)l)[2 * i + 1] = ll[1];
}

// ----------------------------------------------------------------------------
// Fused-split mma.sync NT GEMM: D = Ah*Bh + Al*Bh + Ah*Bl  (fp32 accum).
// Block tile 128(M) x 256(N); K-slices of 64; per slice load Ah/Al/Bh/Bl ONCE
// (cp.async, double-buffered 96KB stages) and compute all 3 products with
// register-resident fragment reuse. 8 warps = 2(M) x 4(N), warp tile 64x64.
// mode 0: bf16 h/l scatter [bh][s][dh]   mode 1: + RoPE   mode 2: fp32 row-major
// ----------------------------------------------------------------------------
#define STG_AH 0
#define STG_AL 16384
#define STG_BH 32768
#define STG_BL 65536
#define STG_SZ 98304
#define GSMEM_SZ (2 * STG_SZ)   // 196608

__device__ __forceinline__ void gemm_mma_body(const __nv_bfloat16* __restrict__ Ah,
                                              const __nv_bfloat16* __restrict__ Al,
                                              const __nv_bfloat16* __restrict__ Bh,
                                              const __nv_bfloat16* __restrict__ Bl,
                                              float* __restrict__ dstf,
                                              __nv_bfloat16* __restrict__ dsth,
                                              __nv_bfloat16* __restrict__ dstl,
                                              int mode) {
    extern __shared__ char smem[];
    const uint32_t sb = smem_u32(smem);
    const int tid  = threadIdx.x;
    const int wid  = tid >> 5, lane = tid & 31;
    const int wm   = wid & 1;          // 64-row half
    const int wn   = wid >> 1;         // 64-col quarter (one head per warp)
    const int m0 = (int)blockIdx.y << 7;
    const int n0 = (int)blockIdx.x << 8;

    const int r8  = tid >> 3;          // 0..31
    const int c16 = tid & 7;           // 16B column unit
    const uint32_t stc = (uint32_t)(c16 << 4);

    // cp.async one K64 slice: Ah/Al (128 rows) + Bh/Bl (256 rows), swizzled
    auto cp_slice = [&](int sl, uint32_t so) {
        const int ko = sl << 6;
#pragma unroll
        for (int r = 0; r < 4; r++) {
            int row = (r << 5) + r8;
            uint32_t off = (uint32_t)(row << 7) + (stc ^ ((row & 7) << 4));
            const size_t g = (size_t)(m0 + row) * DM + ko + (c16 << 3);
            CP16(sb + so + STG_AH + off, (const char*)(Ah + g));
            CP16(sb + so + STG_AL + off, (const char*)(Al + g));
        }
#pragma unroll
        for (int r = 0; r < 8; r++) {
            int row = (r << 5) + r8;
            uint32_t off = (uint32_t)(row << 7) + (stc ^ ((row & 7) << 4));
            const size_t g = (size_t)(n0 + row) * DM + ko + (c16 << 3);
            CP16(sb + so + STG_BH + off, (const char*)(Bh + g));
            CP16(sb + so + STG_BL + off, (const char*)(Bl + g));
        }
    };

    // precomputed swizzled ldmatrix offsets (within a tile)
    uint32_t aoff[4][4], boff[4][4];
    {
        int arow = (wm << 6) + (((lane >> 3) & 1) << 3) + (lane & 7);
        int akb  = ((lane >> 4) & 1) << 4;
        int brow = (wn << 6) + (((lane >> 4) & 1) << 3) + (lane & 7);
        int bkb  = ((lane >> 3) & 1) << 4;
#pragma unroll
        for (int kk = 0; kk < 4; kk++) {
#pragma unroll
            for (int mt = 0; mt < 4; mt++) {
                int row = arow + (mt << 4);
                aoff[mt][kk] = (uint32_t)(row << 7) +
                               (((uint32_t)(kk << 5) + akb) ^ ((row & 7) << 4));
            }
#pragma unroll
            for (int nb = 0; nb < 4; nb++) {
                int row = brow + (nb << 4);
                boff[nb][kk] = (uint32_t)(row << 7) +
                               (((uint32_t)(kk << 5) + bkb) ^ ((row & 7) << 4));
            }
        }
    }

    float acc[4][8][4];
#pragma unroll
    for (int i = 0; i < 4; i++)
#pragma unroll
        for (int j = 0; j < 8; j++)
#pragma unroll
            for (int t = 0; t < 4; t++) acc[i][j][t] = 0.0f;

#define MMA_BLK(afrag, bfrag)                                                  \
    {                                                                          \
        _Pragma("unroll")                                                      \
        for (int mt = 0; mt < 4; mt++)                                         \
            _Pragma("unroll")                                                  \
            for (int nt = 0; nt < 8; nt++)                                     \
                mma16816(acc[mt][nt], afrag[mt],                               \
                         bfrag[nt >> 1][(nt & 1) << 1],                        \
                         bfrag[nt >> 1][((nt & 1) << 1) + 1]);                 \
    }

    cp_slice(0, 0);
    CP_COMMIT();

    for (int c = 0; c < 16; c++) {
        const uint32_t so = (c & 1) ? STG_SZ : 0;
        if (c < 15) {
            cp_slice(c + 1, (c & 1) ? 0 : STG_SZ);   // other buffer: safe, prev
            CP_COMMIT();                             // compute ended with bar
            CP_WAIT1();
        } else {
            CP_WAIT0();
        }
        __syncthreads();

#pragma unroll
        for (int kk = 0; kk < 4; kk++) {
            uint32_t ah4[4][4], al4[4][4], bb[4][4];
#pragma unroll
            for (int mt = 0; mt < 4; mt++) ldsm4(ah4[mt], sb + so + STG_AH + aoff[mt][kk]);
#pragma unroll
            for (int nb = 0; nb < 4; nb++) ldsm4(bb[nb], sb + so + STG_BH + boff[nb][kk]);
            MMA_BLK(ah4, bb);                          // Ah * Bh
#pragma unroll
            for (int mt = 0; mt < 4; mt++) ldsm4(al4[mt], sb + so + STG_AL + aoff[mt][kk]);
            MMA_BLK(al4, bb);                          // Al * Bh
#pragma unroll
            for (int nb = 0; nb < 4; nb++) ldsm4(bb[nb], sb + so + STG_BL + boff[nb][kk]);
            MMA_BLK(ah4, bb);                          // Ah * Bl
        }
        __syncthreads();
    }
#undef MMA_BLK

    // ---- epilogue ----
    const int er = (lane >> 2);
    const int ec = (lane & 3) << 1;
    const int hN = (n0 >> 6) + wn;     // head index for modes 0/1
#pragma unroll
    for (int mt = 0; mt < 4; mt++) {
#pragma unroll
        for (int half = 0; half < 2; half++) {
            int m = m0 + (wm << 6) + (mt << 4) + (half << 3) + er;
            if (mode == 2) {
                float* o = dstf + (size_t)m * DM + n0 + (wn << 6) + ec;
#pragma unroll
                for (int nt = 0; nt < 8; nt++) {
                    o[(nt << 3) + 0] = acc[mt][nt][(half << 1) + 0];
                    o[(nt << 3) + 1] = acc[mt][nt][(half << 1) + 1];
                }
            } else {
                const int b = m >> 11, sidx = m & (S_LEN - 1);
                const size_t rb = ((size_t)((b << 4) + hN) * S_LEN + sidx) * DH;
#pragma unroll
                for (int nt = 0; nt < 8; nt++) {
                    int dh0 = (nt << 3) + ec;
                    float x1 = acc[mt][nt][(half << 1) + 0];
                    float x2 = acc[mt][nt][(half << 1) + 1];
                    if (mode == 1) {
                        float2 cs = g_rope[sidx * (DH / 2) + (dh0 >> 1)];
                        float y1 = x1 * cs.x - x2 * cs.y;
                        float y2 = x1 * cs.y + x2 * cs.x;
                        x1 = y1; x2 = y2;
                    }
                    __nv_bfloat162 hh = __floats2bfloat162_rn(x1, x2);
                    __nv_bfloat162 ll = __floats2bfloat162_rn(
                        x1 - __low2float(hh), x2 - __high2float(hh));
                    *(__nv_bfloat162*)(dsth + rb + dh0) = hh;
                    *(__nv_bfloat162*)(dstl + rb + dh0) = ll;
                }
            }
        }
    }
}

__global__ __launch_bounds__(256, 1) void gemm_mma_qkv(const __nv_bfloat16* __restrict__ xh,
                                                       const __nv_bfloat16* __restrict__ xl,
                                                       const __nv_bfloat16* __restrict__ wh,
                                                       const __nv_bfloat16* __restrict__ wl,
                                                       __nv_bfloat16* qh, __nv_bfloat16* ql,
                                                       __nv_bfloat16* kh, __nv_bfloat16* kl,
                                                       __nv_bfloat16* vh, __nv_bfloat16* vl) {
    const int z = blockIdx.z;
    __nv_bfloat16* dh_ = (z == 0) ? qh : (z == 1) ? kh : vh;
    __nv_bfloat16* dl_ = (z == 0) ? ql : (z == 1) ? kl : vl;
    gemm_mma_body(xh, xl, wh + (size_t)z * DM * DM, wl + (size_t)z * DM * DM,
                  nullptr, dh_, dl_, (z == 2) ? 0 : 1);
}

__global__ __launch_bounds__(256, 1) void gemm_mma_out(const __nv_bfloat16* __restrict__ ah,
                                                       const __nv_bfloat16* __restrict__ al,
                                                       const __nv_bfloat16* __restrict__ wh,
                                                       const __nv_bfloat16* __restrict__ wl,
                                                       float* dst) {
    gemm_mma_body(ah, al, wh, wl, dst, nullptr, nullptr, 2);
}

// ----------------------------------------------------------------------------
// Tensor-core causal flash attention, bf16 hi/lo split, fp32 accum.
// (unchanged from R15 — passing at ~45us)
// ----------------------------------------------------------------------------
#define ATB0 32768
#define ATB1 65536
#define ATK_H 0
#define ATK_L 8192
#define ATV_H 16384
#define ATV_L 24576
#define ASMEM_SZ 98304
#define SCL2E 0.18033688011112042f   // 0.125 * log2(e)

__global__ __launch_bounds__(256) void attn_mma(
    const __nv_bfloat16* __restrict__ qh, const __nv_bfloat16* __restrict__ ql,
    const __nv_bfloat16* __restrict__ kh, const __nv_bfloat16* __restrict__ kl,
    const __nv_bfloat16* __restrict__ vh, const __nv_bfloat16* __restrict__ vl,
    __nv_bfloat16* __restrict__ oh, __nv_bfloat16* __restrict__ ol) {
    extern __shared__ char smem[];
    const uint32_t sb = smem_u32(smem);
    const int tid = threadIdx.x, wid = tid >> 5, lane = tid & 31;
    const int bh = (int)blockIdx.x;
    const int t  = 15 - (int)blockIdx.y;      // heavy tiles first
    const int q0 = t << 7;
    const int ntile = 2 * t + 2;
    const size_t base = (size_t)bh * S_LEN * DH;

    const int r8 = tid >> 3, c16 = tid & 7;
    const uint32_t stc = (uint32_t)(c16 << 4);

#pragma unroll
    for (int k = 0; k < 4; k++) {
        int row = (k << 5) + r8;
        uint32_t d = sb + (row << 7) + (stc ^ ((row & 7) << 4));
        const size_t g = base + (size_t)(q0 + row) * DH + (c16 << 3);
        CP16(d,         (const char*)(qh + g));
        CP16(d + 16384, (const char*)(ql + g));
    }
    auto kv_load = [&](int jt, uint32_t bufofs) {
        int k0 = jt << 6;
#pragma unroll
        for (int r = 0; r < 2; r++) {
            int row = (r << 5) + r8;
            uint32_t d = sb + bufofs + (row << 7) + (stc ^ ((row & 7) << 4));
            const size_t g = base + (size_t)(k0 + row) * DH + (c16 << 3);
            CP16(d + ATK_H, (const char*)(kh + g));
            CP16(d + ATK_L, (const char*)(kl + g));
            CP16(d + ATV_H, (const char*)(vh + g));
            CP16(d + ATV_L, (const char*)(vl + g));
        }
    };
    kv_load(0, ATB0);
    CP_COMMIT();

    const uint32_t swz = (uint32_t)((lane & 7) << 4);
    const uint32_t qrow = (uint32_t)(((wid << 4) + (((lane >> 3) & 1) << 3) + (lane & 7)) << 7);
    const uint32_t akb  = (uint32_t)(((lane >> 4) & 1) << 4);
    const int brow = (((lane >> 4) & 1) << 3) + (lane & 7);
    const uint32_t bkb = (uint32_t)(((lane >> 3) & 1) << 4);
    const int vrow = (((lane >> 3) & 1) << 3) + (lane & 7);
    const uint32_t vnb = (uint32_t)(((lane >> 4) & 1) << 4);

    float O[8][4];
#pragma unroll
    for (int i = 0; i < 8; i++) { O[i][0] = O[i][1] = O[i][2] = O[i][3] = 0.f; }
    float mr0 = -1e30f, mr1 = -1e30f, lr0 = 0.f, lr1 = 0.f;
    const int row0 = q0 + (wid << 4) + (lane >> 2);

    for (int jt = 0; jt < ntile; jt++) {
        const bool more = (jt + 1 < ntile);
        if (more) { kv_load(jt + 1, (jt & 1) ? ATB0 : ATB1); CP_COMMIT(); }
        if (more) { CP_WAIT1(); } else { CP_WAIT0(); }
        __syncthreads();
        const uint32_t bufb = sb + ((jt & 1) ? ATB1 : ATB0);

        float S[8][4];
#pragma unroll
        for (int i = 0; i < 8; i++) { S[i][0] = S[i][1] = S[i][2] = S[i][3] = 0.f; }
#pragma unroll
        for (int kc = 0; kc < 4; kc++) {
            uint32_t qo = sb + qrow + ((((uint32_t)(kc << 5)) | akb) ^ swz);
            uint32_t ah4[4], al4[4];
            ldsm4(ah4, qo);
            ldsm4(al4, qo + 16384);
#pragma unroll
            for (int np = 0; np < 4; np++) {
                uint32_t ko = bufb + (uint32_t)((((np << 4) + brow) << 7)) +
                              ((((uint32_t)(kc << 5)) | bkb) ^ swz);
                uint32_t kf[4];
                ldsm4(kf, ko + ATK_H);
                mma16816(S[2 * np],     ah4, kf[0], kf[1]);
                mma16816(S[2 * np + 1], ah4, kf[2], kf[3]);
                mma16816(S[2 * np],     al4, kf[0], kf[1]);
                mma16816(S[2 * np + 1], al4, kf[2], kf[3]);
                ldsm4(kf, ko + ATK_L);
                mma16816(S[2 * np],     ah4, kf[0], kf[1]);
                mma16816(S[2 * np + 1], ah4, kf[2], kf[3]);
            }
        }

        const bool msk = (jt >= 2 * t);
        const int kbase = (jt << 6) + ((lane & 3) << 1);
        float m0 = -1e30f, m1 = -1e30f;
#pragma unroll
        for (int nt = 0; nt < 8; nt++) {
            float v0 = S[nt][0] * SCL2E, v1 = S[nt][1] * SCL2E;
            float v2 = S[nt][2] * SCL2E, v3 = S[nt][3] * SCL2E;
            if (msk) {
                int kc0 = kbase + (nt << 3);
                if (kc0     > row0)     v0 = -1e30f;
                if (kc0 + 1 > row0)     v1 = -1e30f;
                if (kc0     > row0 + 8) v2 = -1e30f;
                if (kc0 + 1 > row0 + 8) v3 = -1e30f;
            }
            S[nt][0] = v0; S[nt][1] = v1; S[nt][2] = v2; S[nt][3] = v3;
            m0 = fmaxf(m0, fmaxf(v0, v1));
            m1 = fmaxf(m1, fmaxf(v2, v3));
        }
        m0 = fmaxf(m0, __shfl_xor_sync(0xffffffffu, m0, 1));
        m0 = fmaxf(m0, __shfl_xor_sync(0xffffffffu, m0, 2));
        m1 = fmaxf(m1, __shfl_xor_sync(0xffffffffu, m1, 1));
        m1 = fmaxf(m1, __shfl_xor_sync(0xffffffffu, m1, 2));
        float mn0 = fmaxf(mr0, m0), mn1 = fmaxf(mr1, m1);
        float a0 = exp2f(mr0 - mn0), a1 = exp2f(mr1 - mn1);
        mr0 = mn0; mr1 = mn1;

        float s0 = 0.f, s1 = 0.f;
        uint32_t php[8][2], plp[8][2];
#pragma unroll
        for (int nt = 0; nt < 8; nt++) {
            float p0 = exp2f(S[nt][0] - mn0), p1 = exp2f(S[nt][1] - mn0);
            float p2 = exp2f(S[nt][2] - mn1), p3 = exp2f(S[nt][3] - mn1);
            s0 += p0 + p1; s1 += p2 + p3;
            __nv_bfloat162 h01 = __floats2bfloat162_rn(p0, p1);
            __nv_bfloat162 h23 = __floats2bfloat162_rn(p2, p3);
            php[nt][0] = b2u(h01); php[nt][1] = b2u(h23);
            __nv_bfloat162 l01 = __floats2bfloat162_rn(p0 - __low2float(h01),
                                                       p1 - __high2float(h01));
            __nv_bfloat162 l23 = __floats2bfloat162_rn(p2 - __low2float(h23),
                                                       p3 - __high2float(h23));
            plp[nt][0] = b2u(l01); plp[nt][1] = b2u(l23);
            O[nt][0] *= a0; O[nt][1] *= a0; O[nt][2] *= a1; O[nt][3] *= a1;
        }
        s0 += __shfl_xor_sync(0xffffffffu, s0, 1);
        s0 += __shfl_xor_sync(0xffffffffu, s0, 2);
        s1 += __shfl_xor_sync(0xffffffffu, s1, 1);
        s1 += __shfl_xor_sync(0xffffffffu, s1, 2);
        lr0 = lr0 * a0 + s0;
        lr1 = lr1 * a1 + s1;

#pragma unroll
        for (int kc = 0; kc < 4; kc++) {
            uint32_t pah[4] = { php[2 * kc][0], php[2 * kc][1],
                                php[2 * kc + 1][0], php[2 * kc + 1][1] };
            uint32_t pal[4] = { plp[2 * kc][0], plp[2 * kc][1],
                                plp[2 * kc + 1][0], plp[2 * kc + 1][1] };
#pragma unroll
            for (int nv = 0; nv < 4; nv++) {
                uint32_t vo = bufb + (uint32_t)((((kc << 4) + vrow) << 7)) +
                              ((((uint32_t)(nv << 5)) | vnb) ^ swz);
                uint32_t vf[4];
                ldsm4t(vf, vo + ATV_H);
                mma16816(O[2 * nv],     pah, vf[0], vf[1]);
                mma16816(O[2 * nv + 1], pah, vf[2], vf[3]);
                mma16816(O[2 * nv],     pal, vf[0], vf[1]);
                mma16816(O[2 * nv + 1], pal, vf[2], vf[3]);
                ldsm4t(vf, vo + ATV_L);
                mma16816(O[2 * nv],     pah, vf[0], vf[1]);
                mma16816(O[2 * nv + 1], pah, vf[2], vf[3]);
            }
        }
        __syncthreads();
    }

    const float i0 = 1.0f / lr0, i1 = 1.0f / lr1;
    const int b = bh >> 4, h = bh & 15;
    const int gr0 = q0 + (wid << 4) + (lane >> 2);
    const size_t ro0 = ((size_t)(b * S_LEN + gr0)) * DM + (h << 6);
    const size_t ro1 = ro0 + (size_t)8 * DM;
#pragma unroll
    for (int nt = 0; nt < 8; nt++) {
        int dh0 = (nt << 3) + ((lane & 3) << 1);
        float y0 = O[nt][0] * i0, y1 = O[nt][1] * i0;
        float y2 = O[nt][2] * i1, y3 = O[nt][3] * i1;
        __nv_bfloat162 h01 = __floats2bfloat162_rn(y0, y1);
        __nv_bfloat162 l01 = __floats2bfloat162_rn(y0 - __low2float(h01),
                                                   y1 - __high2float(h01));
        *(__nv_bfloat162*)(oh + ro0 + dh0) = h01;
        *(__nv_bfloat162*)(ol + ro0 + dh0) = l01;
        __nv_bfloat162 h23 = __floats2bfloat162_rn(y2, y3);
        __nv_bfloat162 l23 = __floats2bfloat162_rn(y2 - __low2float(h23),
                                                   y3 - __high2float(h23));
        *(__nv_bfloat162*)(oh + ro1 + dh0) = h23;
        *(__nv_bfloat162*)(ol + ro1 + dh0) = l23;
    }
}

// ----------------------------------------------------------------------------
// Launch
// ----------------------------------------------------------------------------
extern "C" void kernel_launch(void* const* d_in, const int* in_sizes, int n_in,
                              void* d_out, int out_size) {
    (void)in_sizes; (void)n_in; (void)out_size;
    const float* X  = (const float*)d_in[0];
    const float* Wq = (const float*)d_in[1];
    const float* Wk = (const float*)d_in[2];
    const float* Wv = (const float*)d_in[3];
    const float* Wo = (const float*)d_in[4];
    float* out = (float*)d_out;

    float2* grope;
    __nv_bfloat16 *xh, *xl, *wh, *wl, *qh, *ql, *kh, *kl, *vh, *vl;
    cudaGetSymbolAddress((void**)&grope, g_rope);
    cudaGetSymbolAddress((void**)&xh, g_xh);
    cudaGetSymbolAddress((void**)&xl, g_xl);
    cudaGetSymbolAddress((void**)&wh, g_wh);
    cudaGetSymbolAddress((void**)&wl, g_wl);
    cudaGetSymbolAddress((void**)&qh, g_qh);
    cudaGetSymbolAddress((void**)&ql, g_ql);
    cudaGetSymbolAddress((void**)&kh, g_kh);
    cudaGetSymbolAddress((void**)&kl, g_kl);
    cudaGetSymbolAddress((void**)&vh, g_vh);
    cudaGetSymbolAddress((void**)&vl, g_vl);

    cudaFuncSetAttribute(gemm_mma_qkv, cudaFuncAttributeMaxDynamicSharedMemorySize, GSMEM_SZ);
    cudaFuncSetAttribute(gemm_mma_out, cudaFuncAttributeMaxDynamicSharedMemorySize, GSMEM_SZ);
    cudaFuncSetAttribute(attn_mma,     cudaFuncAttributeMaxDynamicSharedMemorySize, ASMEM_SZ);

    rope_table_kernel<<<256, 256>>>(grope);

    // bf16 hi/lo splits: input + 4 weight matrices
    split_kernel<<<(MROWS * DM / 4 + 255) / 256, 256>>>(X, xh, xl, MROWS * DM / 4);
    split_kernel<<<(DM * DM / 4 + 255) / 256, 256>>>(Wq, wh + 0 * (size_t)DM * DM, wl + 0 * (size_t)DM * DM, DM * DM / 4);
    split_kernel<<<(DM * DM / 4 + 255) / 256, 256>>>(Wk, wh + 1 * (size_t)DM * DM, wl + 1 * (size_t)DM * DM, DM * DM / 4);
    split_kernel<<<(DM * DM / 4 + 255) / 256, 256>>>(Wv, wh + 2 * (size_t)DM * DM, wl + 2 * (size_t)DM * DM, DM * DM / 4);
    split_kernel<<<(DM * DM / 4 + 255) / 256, 256>>>(Wo, wh + 3 * (size_t)DM * DM, wl + 3 * (size_t)DM * DM, DM * DM / 4);

    // QKV projections (RoPE + bf16 h/l splits in epilogue)
    gemm_mma_qkv<<<dim3(DM / 256, MROWS / 128, 3), 256, GSMEM_SZ>>>(
        xh, xl, wh, wl, qh, ql, kh, kl, vh, vl);

    // tensor-core flash attention -> writes splits straight into xh/xl
    attn_mma<<<dim3(BATCH * NH, S_LEN / 128), 256, ASMEM_SZ>>>(
        qh, ql, kh, kl, vh, vl, xh, xl);

    // output projection
    gemm_mma_out<<<dim3(DM / 256, MROWS / 128), 256, GSMEM_SZ>>>(
        xh, xl, wh + 3 * (size_t)DM * DM, wl + 3 * (size_t)DM * DM, out);
}